// round 2
// baseline (speedup 1.0000x reference)
#include <cuda_runtime.h>
#include <math.h>

// ---------------- problem constants ----------------
#define NIMG   1536            // B*S = 32*48
#define UNITS  48
#define SENS   1283
#define NB     32
#define NS     48

// conv geometry
#define H0 48
#define W0 72
#define H1 23
#define W1 35
#define H2 11
#define W2 17
#define H3 5
#define W3 8

// padded conv0 output: [32][23][36]
#define C0P    (32*23*36)      // 26496 floats per image
#define W1SZ   (64*32*9)       // 18432
#define W2SZ   (32*64*9)       // 18432
#define C1P    (64*11*18)      // 12672 (padded conv1 out in smem)

// ---------------- scratch (device globals; no mallocs allowed) ----------------
__device__ float  g_c0[(size_t)NIMG * C0P];         // conv0 output, padded (~163MB)
__device__ float  g_x [(size_t)NIMG * SENS];        // sensory input x (feat+relpos)
__device__ float  g_sn[(size_t)NIMG * UNITS];       // sensory numerator sums (const folded)
__device__ float  g_sd[(size_t)NIMG * UNITS];       // sensory denominator sums (const folded)
__device__ float4 g_sp[SENS * UNITS];               // fused sensory synapse params
__device__ float4 g_rp[UNITS * UNITS];              // fused recurrent synapse params
__device__ float  g_skn[UNITS], g_skd[UNITS];       // sensory constant sums
__device__ float  g_nc[UNITS], g_dc[UNITS], g_cmt[UNITS];  // ltc per-unit constants

// ---------------- fast math helpers ----------------
__device__ __forceinline__ float rcpf(float x) {
    float y; asm("rcp.approx.f32 %0, %1;" : "=f"(y) : "f"(x)); return y;
}
__device__ __forceinline__ float tanhf_a(float x) {
    float y; asm("tanh.approx.f32 %0, %1;" : "=f"(y) : "f"(x)); return y;
}
// sigmoid(z) = 0.5*tanh(z/2)+0.5 ; params pre-scaled so t = tanh(x*A + C),
// contribution = (0.5*w*erev)*t + const  (const folded per-unit)

// ---------------- prep kernels ----------------
__global__ void k_prep_sens(const float* __restrict__ iw, const float* __restrict__ ib,
                            const float* __restrict__ ssig, const float* __restrict__ smu,
                            const float* __restrict__ sw, const float* __restrict__ serev,
                            const int* __restrict__ smask) {
    int idx = blockIdx.x * blockDim.x + threadIdx.x;
    if (idx >= SENS * UNITS) return;
    int k = idx / UNITS;
    float sg = ssig[idx], m = smu[idx];
    float w  = sw[idx] * (float)smask[idx];
    // z = ((x*iw+ib) - m)*sg ; t = tanh(z/2) = tanh(x*A + C)
    float A = 0.5f * sg * iw[k];
    float C = 0.5f * sg * (ib[k] - m);
    g_sp[idx] = make_float4(A, C, 0.5f * w * serev[idx], 0.5f * w);
}

__global__ void k_prep_rec(const float* __restrict__ sigma, const float* __restrict__ mu,
                           const float* __restrict__ wsyn, const float* __restrict__ erev,
                           const int* __restrict__ mask) {
    int idx = blockIdx.x * blockDim.x + threadIdx.x;
    if (idx >= UNITS * UNITS) return;
    float sg = sigma[idx], m = mu[idx];
    float w  = wsyn[idx] * (float)mask[idx];
    float A = 0.5f * sg;
    float C = -0.5f * sg * m;
    g_rp[idx] = make_float4(A, C, 0.5f * w * erev[idx], 0.5f * w);
}

// per-unit constants (depends on g_sp/g_rp -> launch after the two preps)
__global__ void k_prep_const(const float* __restrict__ gleak, const float* __restrict__ vleak,
                             const float* __restrict__ cm) {
    int u = threadIdx.x;
    if (u >= UNITS) return;
    float kn = 0.f, kd = 0.f;
    for (int k = 0; k < SENS; k++) { float4 p = g_sp[k * UNITS + u]; kn += p.z; kd += p.w; }
    g_skn[u] = kn; g_skd[u] = kd;
    float rn = 0.f, rd = 0.f;
    for (int p = 0; p < UNITS; p++) { float4 q = g_rp[p * UNITS + u]; rn += q.z; rd += q.w; }
    float cmt = cm[u] * 6.f;
    g_cmt[u] = cmt;
    g_nc[u] = gleak[u] * vleak[u] + rn;
    g_dc[u] = cmt + gleak[u] + rd + 1e-8f;
}

// ---------------- conv0: 1->32, 48x72 -> 23x35, writes PADDED layout ----------------
__global__ void __launch_bounds__(512) k_conv0(const float* __restrict__ image,
                                               const float* __restrict__ w0,
                                               const float* __restrict__ b0) {
    __shared__ float simg[H0 * W0];   // 3456
    __shared__ float sw[32 * 9];
    int img = blockIdx.x, tid = threadIdx.x;
    const float* src = image + (size_t)img * (H0 * W0);
    for (int i = tid; i < H0 * W0; i += 512) simg[i] = src[i];
    for (int i = tid; i < 288; i += 512) sw[i] = w0[i];
    __syncthreads();
    // tasks: 16 oc-pairs * 23 oy * 5 ox-groups(7 wide) = 1840
    for (int task = tid; task < 1840; task += 512) {
        int oc0 = (task / 115) * 2;
        int rem = task % 115;
        int oy = rem / 5;
        int ox0 = (rem % 5) * 7;
        float wr0[9], wr1[9];
        #pragma unroll
        for (int j = 0; j < 9; j++) { wr0[j] = sw[oc0 * 9 + j]; wr1[j] = sw[(oc0 + 1) * 9 + j]; }
        float a0[7], a1[7];
        float bb0 = b0[oc0], bb1 = b0[oc0 + 1];
        #pragma unroll
        for (int o = 0; o < 7; o++) { a0[o] = bb0; a1[o] = bb1; }
        #pragma unroll
        for (int ky = 0; ky < 3; ky++) {
            const float* row = &simg[(2 * oy + ky) * W0 + 2 * ox0];
            float r[15];
            #pragma unroll
            for (int j = 0; j < 15; j++) r[j] = row[j];
            #pragma unroll
            for (int kx = 0; kx < 3; kx++) {
                float wa = wr0[ky * 3 + kx], wb = wr1[ky * 3 + kx];
                #pragma unroll
                for (int o = 0; o < 7; o++) {
                    a0[o] = fmaf(wa, r[2 * o + kx], a0[o]);
                    a1[o] = fmaf(wb, r[2 * o + kx], a1[o]);
                }
            }
        }
        // padded layout [oc][oy][36]
        float* out0 = &g_c0[(size_t)img * C0P + oc0 * (23 * 36) + oy * 36 + ox0];
        #pragma unroll
        for (int o = 0; o < 7; o++) {
            out0[o]             = fmaxf(a0[o], 0.f);
            out0[23 * 36 + o]   = fmaxf(a1[o], 0.f);
        }
    }
}

// ---------------- fused conv1 (32->64) + conv2 (64->32) per image ----------------
// 704 threads = 64 oc * 11 oy for conv1 ; conv2 uses 640 tasks.
__global__ void __launch_bounds__(704) k_conv12(const float* __restrict__ w1,
                                                const float* __restrict__ b1,
                                                const float* __restrict__ w2,
                                                const float* __restrict__ b2,
                                                const float* __restrict__ relpos) {
    extern __shared__ float sm[];
    float* sc0 = sm;                 // 26496 floats (padded conv0 input)
    float* sw1 = sm + C0P;           // 18432
    float* sc1 = sm + C0P + W1SZ;    // 12672 (padded conv1 out [64][11][18])
    int img = blockIdx.x, tid = threadIdx.x;

    const float* src = &g_c0[(size_t)img * C0P];
    for (int i = tid; i < C0P; i += 704) sc0[i] = src[i];
    for (int i = tid; i < W1SZ; i += 704) sw1[i] = w1[i];
    __syncthreads();

    // ---- conv1: 1 oc per thread, whole 17-wide output row in regs ----
    {
        int oc = tid / 11;
        int oy = tid % 11;
        float acc[17];
        float bb = __ldg(&b1[oc]);
        #pragma unroll
        for (int o = 0; o < 17; o++) acc[o] = bb;
        for (int ic = 0; ic < 32; ic++) {
            float w[9];
            const float* wp = &sw1[(oc * 32 + ic) * 9];
            #pragma unroll
            for (int j = 0; j < 9; j++) w[j] = wp[j];
            int icbase = ic * (23 * 36);
            #pragma unroll
            for (int ky = 0; ky < 3; ky++) {
                const float4* rowp = reinterpret_cast<const float4*>(&sc0[icbase + (2 * oy + ky) * 36]);
                float r[36];
                #pragma unroll
                for (int j = 0; j < 9; j++) {
                    float4 t = rowp[j];
                    r[4 * j] = t.x; r[4 * j + 1] = t.y; r[4 * j + 2] = t.z; r[4 * j + 3] = t.w;
                }
                #pragma unroll
                for (int kx = 0; kx < 3; kx++) {
                    float wv = w[ky * 3 + kx];
                    #pragma unroll
                    for (int o = 0; o < 17; o++)
                        acc[o] = fmaf(wv, r[2 * o + kx], acc[o]);
                }
            }
        }
        float* outp = &sc1[oc * (11 * 18) + oy * 18];
        #pragma unroll
        for (int o = 0; o < 17; o++) outp[o] = fmaxf(acc[o], 0.f);
    }
    __syncthreads();

    // ---- stage w2 into retired sc0 region ----
    float* sw2 = sc0;
    for (int i = tid; i < W2SZ; i += 704) sw2[i] = w2[i];
    __syncthreads();

    // ---- conv2: 640 tasks = 32 oc * 5 oy * 4 ox-pairs ----
    if (tid < 640) {
        int oc = tid / 20;
        int rem = tid % 20;
        int oy = rem / 4;
        int p  = rem % 4;          // ox pair: outputs 2p, 2p+1
        float a0, a1;
        {
            float bb = __ldg(&b2[oc]);
            a0 = bb; a1 = bb;
        }
        for (int ic = 0; ic < 64; ic++) {
            float w[9];
            const float* wp = &sw2[(oc * 64 + ic) * 9];
            #pragma unroll
            for (int j = 0; j < 9; j++) w[j] = wp[j];
            int icb = ic * (11 * 18);
            #pragma unroll
            for (int ky = 0; ky < 3; ky++) {
                const float* row = &sc1[icb + (2 * oy + ky) * 18 + 4 * p];
                float r[5];
                #pragma unroll
                for (int j = 0; j < 5; j++) r[j] = row[j];
                #pragma unroll
                for (int kx = 0; kx < 3; kx++) {
                    float wv = w[ky * 3 + kx];
                    a0 = fmaf(wv, r[kx], a0);
                    a1 = fmaf(wv, r[kx + 2], a1);
                }
            }
        }
        float* out = &g_x[(size_t)img * SENS + oc * 40 + oy * 8 + 2 * p];
        out[0] = fmaxf(a0, 0.f);
        out[1] = fmaxf(a1, 0.f);
    }
    if (tid < 3) g_x[(size_t)img * SENS + 1280 + tid] = relpos[(size_t)img * 3 + tid];
}

// ---------------- sensory synapse precompute: 16 images/block ----------------
#define SCHUNK 96
#define SIMG   16
__global__ void __launch_bounds__(SIMG * UNITS) k_sens() {
    extern __shared__ float sm2[];
    float4* sp = (float4*)sm2;                      // SCHUNK*48 float4 = 73728B
    float*  xs = sm2 + SCHUNK * UNITS * 4;          // 16*1283 floats = 82112B
    int tid = threadIdx.x;
    int img0 = blockIdx.x * SIMG;
    for (int i = tid; i < SIMG * SENS; i += SIMG * UNITS)
        xs[i] = g_x[(size_t)img0 * SENS + i];
    int u = tid % UNITS, t = tid / UNITS;
    float accn = 0.f, accd = 0.f;
    const float* xrow = &xs[t * SENS];
    for (int k0 = 0; k0 < SENS; k0 += SCHUNK) {
        int C = min(SCHUNK, SENS - k0);
        __syncthreads();
        for (int i = tid; i < C * UNITS; i += SIMG * UNITS) sp[i] = g_sp[k0 * UNITS + i];
        __syncthreads();
        #pragma unroll 4
        for (int kk = 0; kk < C; kk++) {
            float4 p = sp[kk * UNITS + u];
            float xv = xrow[k0 + kk];
            float tt = tanhf_a(fmaf(xv, p.x, p.y));
            accn = fmaf(p.z, tt, accn);
            accd = fmaf(p.w, tt, accd);
        }
    }
    g_sn[(size_t)(img0 + t) * UNITS + u] = g_skn[u] + accn;
    g_sd[(size_t)(img0 + t) * UNITS + u] = g_skd[u] + accd;
}

// ---------------- LTC recurrence + pooling + head ----------------
// one block per batch element; 288 threads = 48 post-units * 6 pre-groups(8)
__global__ void __launch_bounds__(288) k_ltc(const float* __restrict__ wout,
                                             const float* __restrict__ bout,
                                             const float* __restrict__ whead,
                                             const float* __restrict__ bhead,
                                             float* __restrict__ out) {
    extern __shared__ float sm3[];
    float4* rp   = (float4*)sm3;            // 2304 float4 = 9216 floats
    float*  sn   = sm3 + 9216;              // 2304
    float*  sd   = sn + 2304;               // 2304
    float*  v    = sd + 2304;               // 48
    float*  redn = v + 48;                  // 288
    float*  redd = redn + 288;              // 288
    float*  cmt  = redd + 288;              // 48
    float*  nc   = cmt + 48;                // 48
    float*  dc   = nc + 48;                 // 48
    float*  outsum = dc + 48;               // 4
    int b = blockIdx.x, tid = threadIdx.x;
    for (int i = tid; i < UNITS * UNITS; i += 288) rp[i] = g_rp[i];
    for (int i = tid; i < NS * UNITS; i += 288) {
        sn[i] = g_sn[(size_t)b * NS * UNITS + i];
        sd[i] = g_sd[(size_t)b * NS * UNITS + i];
    }
    if (tid < UNITS) {
        v[tid] = 0.f;
        cmt[tid] = g_cmt[tid];
        nc[tid]  = g_nc[tid];
        dc[tid]  = g_dc[tid];
    }
    if (tid < 4) outsum[tid] = 0.f;
    __syncthreads();
    int u = tid % UNITS, g = tid / UNITS;
    for (int s = 0; s < NS; s++) {
        for (int it = 0; it < 6; it++) {
            float accn = 0.f, accd = 0.f;
            #pragma unroll
            for (int j = 0; j < 8; j++) {
                int p = g * 8 + j;
                float4 q = rp[p * UNITS + u];
                float tt = tanhf_a(fmaf(v[p], q.x, q.y));
                accn = fmaf(q.z, tt, accn);
                accd = fmaf(q.w, tt, accd);
            }
            redn[g * UNITS + u] = accn;
            redd[g * UNITS + u] = accd;
            __syncthreads();
            if (tid < UNITS) {
                float a = 0.f, d = 0.f;
                #pragma unroll
                for (int gg = 0; gg < 6; gg++) { a += redn[gg * UNITS + tid]; d += redd[gg * UNITS + tid]; }
                float vv  = v[tid];
                float num = fmaf(cmt[tid], vv, nc[tid]) + a + sn[s * UNITS + tid];
                float den = dc[tid] + d + sd[s * UNITS + tid];
                v[tid] = num * rcpf(den);
            }
            __syncthreads();
        }
        if (tid < 4) outsum[tid] += v[tid];
    }
    __syncthreads();
    if (tid == 0) {
        float p[4];
        #pragma unroll
        for (int m = 0; m < 4; m++)
            p[m] = outsum[m] * (1.f / 48.f) * wout[m] + bout[m];
        #pragma unroll
        for (int j = 0; j < 2; j++) {
            float h = bhead[j];
            #pragma unroll
            for (int m = 0; m < 4; m++) h = fmaf(p[m], whead[m * 2 + j], h);
            out[b * 2 + j] = tanhf(h);
        }
    }
}

// ---------------- launch ----------------
extern "C" void kernel_launch(void* const* d_in, const int* in_sizes, int n_in,
                              void* d_out, int out_size) {
    const float* image   = (const float*)d_in[0];
    const float* rel_pos = (const float*)d_in[1];
    const float* w0 = (const float*)d_in[2];
    const float* b0 = (const float*)d_in[3];
    const float* w1 = (const float*)d_in[4];
    const float* b1 = (const float*)d_in[5];
    const float* w2 = (const float*)d_in[6];
    const float* b2 = (const float*)d_in[7];
    const float* input_w = (const float*)d_in[8];
    const float* input_b = (const float*)d_in[9];
    const float* gleak = (const float*)d_in[10];
    const float* vleak = (const float*)d_in[11];
    const float* cm    = (const float*)d_in[12];
    const float* sigma = (const float*)d_in[13];
    const float* mu    = (const float*)d_in[14];
    const float* w_syn = (const float*)d_in[15];
    const float* erev  = (const float*)d_in[16];
    const float* s_sigma = (const float*)d_in[17];
    const float* s_mu    = (const float*)d_in[18];
    const float* s_w     = (const float*)d_in[19];
    const float* s_erev  = (const float*)d_in[20];
    const float* w_out = (const float*)d_in[21];
    const float* b_out = (const float*)d_in[22];
    const float* w_head = (const float*)d_in[23];
    const float* b_head = (const float*)d_in[24];
    const int* syn_mask  = (const int*)d_in[25];
    const int* sens_mask = (const int*)d_in[26];
    float* out = (float*)d_out;

    const int SM_CONV12 = (C0P + W1SZ + C1P) * 4;                   // 230400
    const int SM_SENS   = SCHUNK * UNITS * 16 + SIMG * SENS * 4;    // 155840
    const int SM_LTC    = (9216 + 2304 + 2304 + 48 + 288 + 288 + 48 + 48 + 48 + 4) * 4;
    cudaFuncSetAttribute(k_conv12, cudaFuncAttributeMaxDynamicSharedMemorySize, SM_CONV12);
    cudaFuncSetAttribute(k_sens,   cudaFuncAttributeMaxDynamicSharedMemorySize, SM_SENS);
    cudaFuncSetAttribute(k_ltc,    cudaFuncAttributeMaxDynamicSharedMemorySize, SM_LTC);

    k_prep_sens<<<(SENS * UNITS + 255) / 256, 256>>>(input_w, input_b, s_sigma, s_mu,
                                                     s_w, s_erev, sens_mask);
    k_prep_rec<<<(UNITS * UNITS + 255) / 256, 256>>>(sigma, mu, w_syn, erev, syn_mask);
    k_prep_const<<<1, UNITS>>>(gleak, vleak, cm);
    k_conv0<<<NIMG, 512>>>(image, w0, b0);
    k_conv12<<<NIMG, 704, SM_CONV12>>>(w1, b1, w2, b2, rel_pos);
    k_sens<<<NIMG / SIMG, SIMG * UNITS, SM_SENS>>>();
    k_ltc<<<NB, 288, SM_LTC>>>(w_out, b_out, w_head, b_head, out);
}

// round 3
// speedup vs baseline: 1.0030x; 1.0030x over previous
#include <cuda_runtime.h>
#include <math.h>

// ---------------- problem constants ----------------
#define NIMG   1536            // B*S = 32*48
#define UNITS  48
#define SENS   1283
#define NB     32
#define NS     48

#define H0 48
#define W0 72

// padded conv0 output: [32][23][36] ; conv1 output: [64][11][18]
#define C0P    (32*23*36)      // 26496 floats per image
#define C1P    (64*11*18)      // 12672 floats per image
#define W1SZ   (64*32*9)       // 18432

// ---------------- scratch (device globals; no mallocs allowed) ----------------
__device__ float  g_c0[(size_t)NIMG * C0P];         // conv0 out, padded (~163MB)
__device__ float  g_c1[(size_t)NIMG * C1P];         // conv1 out, padded (~78MB)
__device__ float  g_x [(size_t)NIMG * SENS];        // sensory input (feat+relpos)
__device__ float  g_sn[(size_t)NIMG * UNITS];
__device__ float  g_sd[(size_t)NIMG * UNITS];
__device__ float4 g_sp[SENS * UNITS];               // fused sensory synapse params
__device__ float4 g_rp[UNITS * UNITS];              // fused recurrent synapse params
__device__ float  g_skn[UNITS], g_skd[UNITS];
__device__ float  g_nc[UNITS], g_dc[UNITS], g_cmt[UNITS];

// ---------------- fast math helpers ----------------
__device__ __forceinline__ float rcpf(float x) {
    float y; asm("rcp.approx.f32 %0, %1;" : "=f"(y) : "f"(x)); return y;
}
__device__ __forceinline__ float tanhf_a(float x) {
    float y; asm("tanh.approx.f32 %0, %1;" : "=f"(y) : "f"(x)); return y;
}

// compile-time float4 component select (v must be a constant after unroll)
#define RV(t, v) ((v) % 4 == 0 ? t[(v) / 4].x : (v) % 4 == 1 ? t[(v) / 4].y \
                 : (v) % 4 == 2 ? t[(v) / 4].z : t[(v) / 4].w)

// ---------------- prep kernels ----------------
__global__ void k_prep_sens(const float* __restrict__ iw, const float* __restrict__ ib,
                            const float* __restrict__ ssig, const float* __restrict__ smu,
                            const float* __restrict__ sw, const float* __restrict__ serev,
                            const int* __restrict__ smask) {
    int idx = blockIdx.x * blockDim.x + threadIdx.x;
    if (idx >= SENS * UNITS) return;
    int k = idx / UNITS;
    float sg = ssig[idx], m = smu[idx];
    float w  = sw[idx] * (float)smask[idx];
    float A = 0.5f * sg * iw[k];
    float C = 0.5f * sg * (ib[k] - m);
    g_sp[idx] = make_float4(A, C, 0.5f * w * serev[idx], 0.5f * w);
}

__global__ void k_prep_rec(const float* __restrict__ sigma, const float* __restrict__ mu,
                           const float* __restrict__ wsyn, const float* __restrict__ erev,
                           const int* __restrict__ mask) {
    int idx = blockIdx.x * blockDim.x + threadIdx.x;
    if (idx >= UNITS * UNITS) return;
    float sg = sigma[idx], m = mu[idx];
    float w  = wsyn[idx] * (float)mask[idx];
    g_rp[idx] = make_float4(0.5f * sg, -0.5f * sg * m, 0.5f * w * erev[idx], 0.5f * w);
}

__global__ void k_prep_const(const float* __restrict__ gleak, const float* __restrict__ vleak,
                             const float* __restrict__ cm) {
    int u = threadIdx.x;
    if (u >= UNITS) return;
    float kn = 0.f, kd = 0.f;
    for (int k = 0; k < SENS; k++) { float4 p = g_sp[k * UNITS + u]; kn += p.z; kd += p.w; }
    g_skn[u] = kn; g_skd[u] = kd;
    float rn = 0.f, rd = 0.f;
    for (int p = 0; p < UNITS; p++) { float4 q = g_rp[p * UNITS + u]; rn += q.z; rd += q.w; }
    float cmt = cm[u] * 6.f;
    g_cmt[u] = cmt;
    g_nc[u] = gleak[u] * vleak[u] + rn;
    g_dc[u] = cmt + gleak[u] + rd + 1e-8f;
}

// ---------------- conv0: 1->32, 48x72 -> 23x35 padded, warp-per-row ----------------
__global__ void __launch_bounds__(512) k_conv0(const float* __restrict__ image,
                                               const float* __restrict__ w0,
                                               const float* __restrict__ b0) {
    __shared__ float simg[H0 * W0];   // 3456
    __shared__ float sw[32 * 9];
    __shared__ float sb[32];
    int img = blockIdx.x, tid = threadIdx.x;
    const float4* src = (const float4*)(image + (size_t)img * (H0 * W0));
    float4* dimg = (float4*)simg;
    for (int i = tid; i < (H0 * W0) / 4; i += 512) dimg[i] = src[i];
    for (int i = tid; i < 288; i += 512) sw[i] = w0[i];
    if (tid < 32) sb[tid] = b0[tid];
    __syncthreads();
    int wid = tid >> 5, lane = tid & 31;
    // 736 row-tasks = 32 oc * 23 oy ; 16 warps
    for (int task = wid; task < 736; task += 16) {
        int oc = task / 23;
        int oy = task % 23;
        float w[9];
        #pragma unroll
        for (int j = 0; j < 9; j++) w[j] = sw[oc * 9 + j];
        float bb = sb[oc];
        float a = bb;
        #pragma unroll
        for (int ky = 0; ky < 3; ky++) {
            const float* row = &simg[(2 * oy + ky) * W0 + 2 * lane];
            #pragma unroll
            for (int kx = 0; kx < 3; kx++)
                a = fmaf(w[ky * 3 + kx], row[kx], a);
        }
        float* outr = &g_c0[(size_t)img * C0P + oc * (23 * 36) + oy * 36];
        outr[lane] = fmaxf(a, 0.f);
        if (lane < 3) {   // ox = 32..34
            int ox = 32 + lane;
            float a2 = bb;
            #pragma unroll
            for (int ky = 0; ky < 3; ky++) {
                const float* row = &simg[(2 * oy + ky) * W0 + 2 * ox];
                #pragma unroll
                for (int kx = 0; kx < 3; kx++)
                    a2 = fmaf(w[ky * 3 + kx], row[kx], a2);
            }
            outr[ox] = fmaxf(a2, 0.f);
        }
    }
}

// ---------------- conv1: 32->64, 23x35(pad36) -> 11x17(pad18) ----------------
// 704 threads = 64 oc * 11 oy ; row kept as 9 float4 regs (no scalar copy)
__global__ void __launch_bounds__(704) k_conv1(const float* __restrict__ w1,
                                               const float* __restrict__ b1) {
    extern __shared__ float sm[];
    float* sc0 = sm;            // 26496
    float* sw1 = sm + C0P;      // 18432
    int img = blockIdx.x, tid = threadIdx.x;
    {
        const float4* src = (const float4*)&g_c0[(size_t)img * C0P];
        float4* d = (float4*)sc0;
        for (int i = tid; i < C0P / 4; i += 704) d[i] = src[i];
        const float4* ws = (const float4*)w1;
        float4* dw = (float4*)sw1;
        for (int i = tid; i < W1SZ / 4; i += 704) dw[i] = ws[i];
    }
    __syncthreads();
    int oc = tid / 11;
    int oy = tid % 11;
    float acc[17];
    float bb = __ldg(&b1[oc]);
    #pragma unroll
    for (int o = 0; o < 17; o++) acc[o] = bb;
    for (int ic = 0; ic < 32; ic++) {
        float w[9];
        const float* wp = &sw1[(oc * 32 + ic) * 9];
        #pragma unroll
        for (int j = 0; j < 9; j++) w[j] = wp[j];
        int icb = ic * (23 * 36);
        #pragma unroll
        for (int ky = 0; ky < 3; ky++) {
            const float4* rp = (const float4*)&sc0[icb + (2 * oy + ky) * 36];
            float4 t[9];
            #pragma unroll
            for (int j = 0; j < 9; j++) t[j] = rp[j];
            #pragma unroll
            for (int kx = 0; kx < 3; kx++) {
                float wv = w[ky * 3 + kx];
                #pragma unroll
                for (int o = 0; o < 17; o++)
                    acc[o] = fmaf(wv, RV(t, 2 * o + kx), acc[o]);
            }
        }
    }
    float* outp = &g_c1[(size_t)img * C1P + oc * (11 * 18) + oy * 18];
    #pragma unroll
    for (int o = 0; o < 17; o++) outp[o] = fmaxf(acc[o], 0.f);
}

// ---------------- conv2: 64->32, 11x17(pad18) -> 5x8 ; writes g_x ----------------
// 320 threads = 32 oc * 5 oy * 2 ox-groups(4 wide) ; input staged (50KB smem)
__global__ void __launch_bounds__(320) k_conv2(const float* __restrict__ w2,
                                               const float* __restrict__ b2,
                                               const float* __restrict__ relpos) {
    extern __shared__ float sc1[];   // 12672 floats
    int img = blockIdx.x, tid = threadIdx.x;
    {
        const float2* src = (const float2*)&g_c1[(size_t)img * C1P];
        float2* d = (float2*)sc1;
        for (int i = tid; i < C1P / 2; i += 320) d[i] = src[i];
    }
    __syncthreads();
    int oc = tid / 10;
    int rem = tid % 10;
    int oy = rem / 2;
    int p  = rem % 2;       // ox group: outputs 4p..4p+3
    float a[4];
    {
        float bb = __ldg(&b2[oc]);
        #pragma unroll
        for (int o = 0; o < 4; o++) a[o] = bb;
    }
    for (int ic = 0; ic < 64; ic++) {
        float w[9];
        const float* wp = &w2[((size_t)oc * 64 + ic) * 9];
        #pragma unroll
        for (int j = 0; j < 9; j++) w[j] = __ldg(&wp[j]);
        int icb = ic * (11 * 18);
        #pragma unroll
        for (int ky = 0; ky < 3; ky++) {
            const float* row = &sc1[icb + (2 * oy + ky) * 18 + 8 * p];
            float r[9];
            #pragma unroll
            for (int j = 0; j < 9; j++) r[j] = row[j];
            #pragma unroll
            for (int kx = 0; kx < 3; kx++) {
                float wv = w[ky * 3 + kx];
                #pragma unroll
                for (int o = 0; o < 4; o++)
                    a[o] = fmaf(wv, r[2 * o + kx], a[o]);
            }
        }
    }
    float* out = &g_x[(size_t)img * SENS + oc * 40 + oy * 8 + 4 * p];
    #pragma unroll
    for (int o = 0; o < 4; o++) out[o] = fmaxf(a[o], 0.f);
    if (tid < 3) g_x[(size_t)img * SENS + 1280 + tid] = relpos[(size_t)img * 3 + tid];
}

// ---------------- sensory synapse precompute: 12 images/block (128 blocks) ------
#define SCHUNK 96
#define SIMG   12
__global__ void __launch_bounds__(SIMG * UNITS) k_sens() {
    extern __shared__ float sm2[];
    float4* sp = (float4*)sm2;                      // SCHUNK*48 float4 = 73728B
    float*  xs = sm2 + SCHUNK * UNITS * 4;          // 12*1283 floats
    int tid = threadIdx.x;
    int img0 = blockIdx.x * SIMG;
    for (int i = tid; i < SIMG * SENS; i += SIMG * UNITS)
        xs[i] = g_x[(size_t)img0 * SENS + i];
    int u = tid % UNITS, t = tid / UNITS;
    float accn = 0.f, accd = 0.f;
    const float* xrow = &xs[t * SENS];
    for (int k0 = 0; k0 < SENS; k0 += SCHUNK) {
        int C = min(SCHUNK, SENS - k0);
        __syncthreads();
        for (int i = tid; i < C * UNITS; i += SIMG * UNITS) sp[i] = g_sp[k0 * UNITS + i];
        __syncthreads();
        #pragma unroll 4
        for (int kk = 0; kk < C; kk++) {
            float4 p = sp[kk * UNITS + u];
            float xv = xrow[k0 + kk];
            float tt = tanhf_a(fmaf(xv, p.x, p.y));
            accn = fmaf(p.z, tt, accn);
            accd = fmaf(p.w, tt, accd);
        }
    }
    g_sn[(size_t)(img0 + t) * UNITS + u] = g_skn[u] + accn;
    g_sd[(size_t)(img0 + t) * UNITS + u] = g_skd[u] + accd;
}

// ---------------- LTC recurrence + pooling + head ----------------
__global__ void __launch_bounds__(288) k_ltc(const float* __restrict__ wout,
                                             const float* __restrict__ bout,
                                             const float* __restrict__ whead,
                                             const float* __restrict__ bhead,
                                             float* __restrict__ out) {
    extern __shared__ float sm3[];
    float4* rp   = (float4*)sm3;            // 9216 floats
    float*  sn   = sm3 + 9216;              // 2304
    float*  sd   = sn + 2304;               // 2304
    float*  v    = sd + 2304;               // 48
    float*  redn = v + 48;                  // 288
    float*  redd = redn + 288;              // 288
    float*  cmt  = redd + 288;              // 48
    float*  nc   = cmt + 48;                // 48
    float*  dc   = nc + 48;                 // 48
    float*  outsum = dc + 48;               // 4
    int b = blockIdx.x, tid = threadIdx.x;
    for (int i = tid; i < UNITS * UNITS; i += 288) rp[i] = g_rp[i];
    for (int i = tid; i < NS * UNITS; i += 288) {
        sn[i] = g_sn[(size_t)b * NS * UNITS + i];
        sd[i] = g_sd[(size_t)b * NS * UNITS + i];
    }
    if (tid < UNITS) {
        v[tid] = 0.f;
        cmt[tid] = g_cmt[tid];
        nc[tid]  = g_nc[tid];
        dc[tid]  = g_dc[tid];
    }
    if (tid < 4) outsum[tid] = 0.f;
    __syncthreads();
    int u = tid % UNITS, g = tid / UNITS;
    for (int s = 0; s < NS; s++) {
        for (int it = 0; it < 6; it++) {
            float accn = 0.f, accd = 0.f;
            #pragma unroll
            for (int j = 0; j < 8; j++) {
                int p = g * 8 + j;
                float4 q = rp[p * UNITS + u];
                float tt = tanhf_a(fmaf(v[p], q.x, q.y));
                accn = fmaf(q.z, tt, accn);
                accd = fmaf(q.w, tt, accd);
            }
            redn[g * UNITS + u] = accn;
            redd[g * UNITS + u] = accd;
            __syncthreads();
            if (tid < UNITS) {
                float a = 0.f, d = 0.f;
                #pragma unroll
                for (int gg = 0; gg < 6; gg++) { a += redn[gg * UNITS + tid]; d += redd[gg * UNITS + tid]; }
                float vv  = v[tid];
                float num = fmaf(cmt[tid], vv, nc[tid]) + a + sn[s * UNITS + tid];
                float den = dc[tid] + d + sd[s * UNITS + tid];
                v[tid] = num * rcpf(den);
            }
            __syncthreads();
        }
        if (tid < 4) outsum[tid] += v[tid];
    }
    __syncthreads();
    if (tid == 0) {
        float p[4];
        #pragma unroll
        for (int m = 0; m < 4; m++)
            p[m] = outsum[m] * (1.f / 48.f) * wout[m] + bout[m];
        #pragma unroll
        for (int j = 0; j < 2; j++) {
            float h = bhead[j];
            #pragma unroll
            for (int m = 0; m < 4; m++) h = fmaf(p[m], whead[m * 2 + j], h);
            out[b * 2 + j] = tanhf(h);
        }
    }
}

// ---------------- launch ----------------
extern "C" void kernel_launch(void* const* d_in, const int* in_sizes, int n_in,
                              void* d_out, int out_size) {
    const float* image   = (const float*)d_in[0];
    const float* rel_pos = (const float*)d_in[1];
    const float* w0 = (const float*)d_in[2];
    const float* b0 = (const float*)d_in[3];
    const float* w1 = (const float*)d_in[4];
    const float* b1 = (const float*)d_in[5];
    const float* w2 = (const float*)d_in[6];
    const float* b2 = (const float*)d_in[7];
    const float* input_w = (const float*)d_in[8];
    const float* input_b = (const float*)d_in[9];
    const float* gleak = (const float*)d_in[10];
    const float* vleak = (const float*)d_in[11];
    const float* cm    = (const float*)d_in[12];
    const float* sigma = (const float*)d_in[13];
    const float* mu    = (const float*)d_in[14];
    const float* w_syn = (const float*)d_in[15];
    const float* erev  = (const float*)d_in[16];
    const float* s_sigma = (const float*)d_in[17];
    const float* s_mu    = (const float*)d_in[18];
    const float* s_w     = (const float*)d_in[19];
    const float* s_erev  = (const float*)d_in[20];
    const float* w_out = (const float*)d_in[21];
    const float* b_out = (const float*)d_in[22];
    const float* w_head = (const float*)d_in[23];
    const float* b_head = (const float*)d_in[24];
    const int* syn_mask  = (const int*)d_in[25];
    const int* sens_mask = (const int*)d_in[26];
    float* out = (float*)d_out;

    const int SM_CONV1 = (C0P + W1SZ) * 4;                          // 179712
    const int SM_CONV2 = C1P * 4;                                   // 50688
    const int SM_SENS  = SCHUNK * UNITS * 16 + SIMG * SENS * 4;     // 135324 -> pad
    const int SM_LTC   = (9216 + 2304 + 2304 + 48 + 288 + 288 + 48 + 48 + 48 + 4) * 4;
    cudaFuncSetAttribute(k_conv1, cudaFuncAttributeMaxDynamicSharedMemorySize, SM_CONV1);
    cudaFuncSetAttribute(k_conv2, cudaFuncAttributeMaxDynamicSharedMemorySize, SM_CONV2);
    cudaFuncSetAttribute(k_sens,  cudaFuncAttributeMaxDynamicSharedMemorySize, SM_SENS);
    cudaFuncSetAttribute(k_ltc,   cudaFuncAttributeMaxDynamicSharedMemorySize, SM_LTC);

    k_prep_sens<<<(SENS * UNITS + 255) / 256, 256>>>(input_w, input_b, s_sigma, s_mu,
                                                     s_w, s_erev, sens_mask);
    k_prep_rec<<<(UNITS * UNITS + 255) / 256, 256>>>(sigma, mu, w_syn, erev, syn_mask);
    k_prep_const<<<1, UNITS>>>(gleak, vleak, cm);
    k_conv0<<<NIMG, 512>>>(image, w0, b0);
    k_conv1<<<NIMG, 704, SM_CONV1>>>(w1, b1);
    k_conv2<<<NIMG, 320, SM_CONV2>>>(w2, b2, rel_pos);
    k_sens<<<NIMG / SIMG, SIMG * UNITS, SM_SENS>>>();
    k_ltc<<<NB, 288, SM_LTC>>>(w_out, b_out, w_head, b_head, out);
}

// round 4
// speedup vs baseline: 1.2787x; 1.2750x over previous
#include <cuda_runtime.h>
#include <math.h>

// ---------------- problem constants ----------------
#define NIMG   1536            // B*S = 32*48
#define UNITS  48
#define SENS   1283
#define NB     32
#define NS     48

#define H0 48
#define W0 72

// padded conv0 output: [32][23][36] ; conv1 output: [64][11][18]
#define C0P    (32*23*36)      // 26496 floats per image
#define C1P    (64*11*18)      // 12672 floats per image
#define W1SZ   (64*32*9)       // 18432
#define W2SZ   (32*64*9)       // 18432

// ---------------- scratch (device globals; no mallocs allowed) ----------------
__device__ float  g_c0[(size_t)NIMG * C0P];         // conv0 out, padded (~163MB)
__device__ float  g_c1[(size_t)NIMG * C1P];         // conv1 out, padded (~78MB)
__device__ float  g_x [(size_t)NIMG * SENS];        // sensory input (feat+relpos)
__device__ float  g_sn[(size_t)NIMG * UNITS];
__device__ float  g_sd[(size_t)NIMG * UNITS];
__device__ float4 g_sp[SENS * UNITS];               // fused sensory synapse params
__device__ float4 g_rp[UNITS * UNITS];              // fused recurrent synapse params
__device__ float  g_skn[UNITS], g_skd[UNITS];
__device__ float  g_nc[UNITS], g_dc[UNITS], g_cmt[UNITS];

// ---------------- fast math helpers ----------------
__device__ __forceinline__ float rcpf(float x) {
    float y; asm("rcp.approx.f32 %0, %1;" : "=f"(y) : "f"(x)); return y;
}
__device__ __forceinline__ float tanhf_a(float x) {
    float y; asm("tanh.approx.f32 %0, %1;" : "=f"(y) : "f"(x)); return y;
}

// compile-time float4 component select (v must be a constant after unroll)
#define RV(t, v) ((v) % 4 == 0 ? t[(v) / 4].x : (v) % 4 == 1 ? t[(v) / 4].y \
                 : (v) % 4 == 2 ? t[(v) / 4].z : t[(v) / 4].w)

// ---------------- prep kernels ----------------
__global__ void k_prep_sens(const float* __restrict__ iw, const float* __restrict__ ib,
                            const float* __restrict__ ssig, const float* __restrict__ smu,
                            const float* __restrict__ sw, const float* __restrict__ serev,
                            const int* __restrict__ smask) {
    int idx = blockIdx.x * blockDim.x + threadIdx.x;
    if (idx >= SENS * UNITS) return;
    int k = idx / UNITS;
    float sg = ssig[idx], m = smu[idx];
    float w  = sw[idx] * (float)smask[idx];
    float A = 0.5f * sg * iw[k];
    float C = 0.5f * sg * (ib[k] - m);
    g_sp[idx] = make_float4(A, C, 0.5f * w * serev[idx], 0.5f * w);
}

__global__ void k_prep_rec(const float* __restrict__ sigma, const float* __restrict__ mu,
                           const float* __restrict__ wsyn, const float* __restrict__ erev,
                           const int* __restrict__ mask) {
    int idx = blockIdx.x * blockDim.x + threadIdx.x;
    if (idx >= UNITS * UNITS) return;
    float sg = sigma[idx], m = mu[idx];
    float w  = wsyn[idx] * (float)mask[idx];
    g_rp[idx] = make_float4(0.5f * sg, -0.5f * sg * m, 0.5f * w * erev[idx], 0.5f * w);
}

// one block per unit; block-reduce the sensory constant sums
__global__ void __launch_bounds__(256) k_prep_const(const float* __restrict__ gleak,
                                                    const float* __restrict__ vleak,
                                                    const float* __restrict__ cm) {
    int u = blockIdx.x, tid = threadIdx.x;
    float kn = 0.f, kd = 0.f;
    for (int k = tid; k < SENS; k += 256) {
        float4 p = g_sp[k * UNITS + u];
        kn += p.z; kd += p.w;
    }
    #pragma unroll
    for (int o = 16; o > 0; o >>= 1) {
        kn += __shfl_xor_sync(0xffffffff, kn, o);
        kd += __shfl_xor_sync(0xffffffff, kd, o);
    }
    __shared__ float swn[8], swd[8];
    if ((tid & 31) == 0) { swn[tid >> 5] = kn; swd[tid >> 5] = kd; }
    __syncthreads();
    if (tid == 0) {
        float tn = 0.f, td = 0.f;
        #pragma unroll
        for (int i = 0; i < 8; i++) { tn += swn[i]; td += swd[i]; }
        g_skn[u] = tn; g_skd[u] = td;
        float rn = 0.f, rd = 0.f;
        for (int p = 0; p < UNITS; p++) { float4 q = g_rp[p * UNITS + u]; rn += q.z; rd += q.w; }
        float cmt = cm[u] * 6.f;
        g_cmt[u] = cmt;
        g_nc[u] = gleak[u] * vleak[u] + rn;
        g_dc[u] = cmt + gleak[u] + rd + 1e-8f;
    }
}

// ---------------- conv0: 1->32, 48x72 -> 23x35 padded, warp-per-row ----------------
__global__ void __launch_bounds__(512) k_conv0(const float* __restrict__ image,
                                               const float* __restrict__ w0,
                                               const float* __restrict__ b0) {
    __shared__ float simg[H0 * W0];   // 3456
    __shared__ float sw[32 * 9];
    __shared__ float sb[32];
    int img = blockIdx.x, tid = threadIdx.x;
    const float4* src = (const float4*)(image + (size_t)img * (H0 * W0));
    float4* dimg = (float4*)simg;
    for (int i = tid; i < (H0 * W0) / 4; i += 512) dimg[i] = src[i];
    for (int i = tid; i < 288; i += 512) sw[i] = w0[i];
    if (tid < 32) sb[tid] = b0[tid];
    __syncthreads();
    int wid = tid >> 5, lane = tid & 31;
    for (int task = wid; task < 736; task += 16) {
        int oc = task / 23;
        int oy = task % 23;
        float w[9];
        #pragma unroll
        for (int j = 0; j < 9; j++) w[j] = sw[oc * 9 + j];
        float bb = sb[oc];
        float a = bb;
        #pragma unroll
        for (int ky = 0; ky < 3; ky++) {
            const float* row = &simg[(2 * oy + ky) * W0 + 2 * lane];
            #pragma unroll
            for (int kx = 0; kx < 3; kx++)
                a = fmaf(w[ky * 3 + kx], row[kx], a);
        }
        float* outr = &g_c0[(size_t)img * C0P + oc * (23 * 36) + oy * 36];
        outr[lane] = fmaxf(a, 0.f);
        if (lane < 3) {
            int ox = 32 + lane;
            float a2 = bb;
            #pragma unroll
            for (int ky = 0; ky < 3; ky++) {
                const float* row = &simg[(2 * oy + ky) * W0 + 2 * ox];
                #pragma unroll
                for (int kx = 0; kx < 3; kx++)
                    a2 = fmaf(w[ky * 3 + kx], row[kx], a2);
            }
            outr[ox] = fmaxf(a2, 0.f);
        }
    }
}

// ---------------- conv1: 32->64, 23x35(pad36) -> 11x17(pad18) ----------------
// 352 threads = 32 oc-pairs * 11 oy ; 186-reg cap, no spill; float4 row loads
__global__ void __launch_bounds__(352) k_conv1(const float* __restrict__ w1,
                                               const float* __restrict__ b1) {
    extern __shared__ float sm[];
    float* sc0 = sm;            // 26496
    float* sw1 = sm + C0P;      // 18432
    int img = blockIdx.x, tid = threadIdx.x;
    {
        const float4* src = (const float4*)&g_c0[(size_t)img * C0P];
        float4* d = (float4*)sc0;
        for (int i = tid; i < C0P / 4; i += 352) d[i] = src[i];
        const float4* ws = (const float4*)w1;
        float4* dw = (float4*)sw1;
        for (int i = tid; i < W1SZ / 4; i += 352) dw[i] = ws[i];
    }
    __syncthreads();
    int oc0 = (tid / 11) * 2;
    int oy  = tid % 11;
    float a0[17], a1[17];
    float bb0 = __ldg(&b1[oc0]), bb1 = __ldg(&b1[oc0 + 1]);
    #pragma unroll
    for (int o = 0; o < 17; o++) { a0[o] = bb0; a1[o] = bb1; }
    for (int ic = 0; ic < 32; ic++) {
        float w0r[9], w1r[9];
        const float* wp0 = &sw1[(oc0 * 32 + ic) * 9];
        const float* wp1 = &sw1[((oc0 + 1) * 32 + ic) * 9];
        #pragma unroll
        for (int j = 0; j < 9; j++) { w0r[j] = wp0[j]; w1r[j] = wp1[j]; }
        int icb = ic * (23 * 36);
        #pragma unroll
        for (int ky = 0; ky < 3; ky++) {
            const float4* rp = (const float4*)&sc0[icb + (2 * oy + ky) * 36];
            float4 t[9];
            #pragma unroll
            for (int j = 0; j < 9; j++) t[j] = rp[j];
            #pragma unroll
            for (int kx = 0; kx < 3; kx++) {
                float wa = w0r[ky * 3 + kx], wb = w1r[ky * 3 + kx];
                #pragma unroll
                for (int o = 0; o < 17; o++) {
                    a0[o] = fmaf(wa, RV(t, 2 * o + kx), a0[o]);
                    a1[o] = fmaf(wb, RV(t, 2 * o + kx), a1[o]);
                }
            }
        }
    }
    float* outp = &g_c1[(size_t)img * C1P + oc0 * (11 * 18) + oy * 18];
    #pragma unroll
    for (int o = 0; o < 17; o++) {
        outp[o]            = fmaxf(a0[o], 0.f);
        outp[11 * 18 + o]  = fmaxf(a1[o], 0.f);
    }
}

// ---------------- conv2: 64->32, 11x17(pad18) -> 5x8 ; writes g_x ----------------
// 320 threads = 32 oc * 5 oy * 2 ox-groups(4) ; input + weights staged in smem
__global__ void __launch_bounds__(320) k_conv2(const float* __restrict__ w2,
                                               const float* __restrict__ b2,
                                               const float* __restrict__ relpos) {
    extern __shared__ float sm2[];
    float* sc1 = sm2;            // 12672
    float* sw2 = sm2 + C1P;      // 18432
    int img = blockIdx.x, tid = threadIdx.x;
    {
        const float4* src = (const float4*)&g_c1[(size_t)img * C1P];
        float4* d = (float4*)sc1;
        for (int i = tid; i < C1P / 4; i += 320) d[i] = src[i];
        const float4* ws = (const float4*)w2;
        float4* dw = (float4*)sw2;
        for (int i = tid; i < W2SZ / 4; i += 320) dw[i] = ws[i];
    }
    __syncthreads();
    int oc = tid / 10;
    int rem = tid % 10;
    int oy = rem / 2;
    int p  = rem % 2;
    float a[4];
    {
        float bb = __ldg(&b2[oc]);
        #pragma unroll
        for (int o = 0; o < 4; o++) a[o] = bb;
    }
    for (int ic = 0; ic < 64; ic++) {
        float w[9];
        const float* wp = &sw2[(oc * 64 + ic) * 9];
        #pragma unroll
        for (int j = 0; j < 9; j++) w[j] = wp[j];
        int icb = ic * (11 * 18);
        #pragma unroll
        for (int ky = 0; ky < 3; ky++) {
            const float* row = &sc1[icb + (2 * oy + ky) * 18 + 8 * p];
            float r[9];
            #pragma unroll
            for (int j = 0; j < 9; j++) r[j] = row[j];
            #pragma unroll
            for (int kx = 0; kx < 3; kx++) {
                float wv = w[ky * 3 + kx];
                #pragma unroll
                for (int o = 0; o < 4; o++)
                    a[o] = fmaf(wv, r[2 * o + kx], a[o]);
            }
        }
    }
    float* out = &g_x[(size_t)img * SENS + oc * 40 + oy * 8 + 4 * p];
    #pragma unroll
    for (int o = 0; o < 4; o++) out[o] = fmaxf(a[o], 0.f);
    if (tid < 3) g_x[(size_t)img * SENS + 1280 + tid] = relpos[(size_t)img * 3 + tid];
}

// ---------------- sensory synapse precompute: 12 images/block (128 blocks) ------
#define SCHUNK 96
#define SIMG   12
__global__ void __launch_bounds__(SIMG * UNITS) k_sens() {
    extern __shared__ float sm3[];
    float4* sp = (float4*)sm3;                      // SCHUNK*48 float4 = 73728B
    float*  xs = sm3 + SCHUNK * UNITS * 4;          // 12*1283 floats
    int tid = threadIdx.x;
    int img0 = blockIdx.x * SIMG;
    for (int i = tid; i < SIMG * SENS; i += SIMG * UNITS)
        xs[i] = g_x[(size_t)img0 * SENS + i];
    int u = tid % UNITS, t = tid / UNITS;
    float accn = 0.f, accd = 0.f;
    const float* xrow = &xs[t * SENS];
    for (int k0 = 0; k0 < SENS; k0 += SCHUNK) {
        int C = min(SCHUNK, SENS - k0);
        __syncthreads();
        for (int i = tid; i < C * UNITS; i += SIMG * UNITS) sp[i] = g_sp[k0 * UNITS + i];
        __syncthreads();
        #pragma unroll 4
        for (int kk = 0; kk < C; kk++) {
            float4 p = sp[kk * UNITS + u];
            float xv = xrow[k0 + kk];
            float tt = tanhf_a(fmaf(xv, p.x, p.y));
            accn = fmaf(p.z, tt, accn);
            accd = fmaf(p.w, tt, accd);
        }
    }
    g_sn[(size_t)(img0 + t) * UNITS + u] = g_skn[u] + accn;
    g_sd[(size_t)(img0 + t) * UNITS + u] = g_skd[u] + accd;
}

// ---------------- LTC recurrence + pooling + head ----------------
__global__ void __launch_bounds__(288) k_ltc(const float* __restrict__ wout,
                                             const float* __restrict__ bout,
                                             const float* __restrict__ whead,
                                             const float* __restrict__ bhead,
                                             float* __restrict__ out) {
    extern __shared__ float sm4[];
    float4* rp   = (float4*)sm4;            // 9216 floats
    float*  sn   = sm4 + 9216;              // 2304
    float*  sd   = sn + 2304;               // 2304
    float*  v    = sd + 2304;               // 48
    float*  redn = v + 48;                  // 288
    float*  redd = redn + 288;              // 288
    float*  cmt  = redd + 288;              // 48
    float*  nc   = cmt + 48;                // 48
    float*  dc   = nc + 48;                 // 48
    float*  outsum = dc + 48;               // 4
    int b = blockIdx.x, tid = threadIdx.x;
    for (int i = tid; i < UNITS * UNITS; i += 288) rp[i] = g_rp[i];
    for (int i = tid; i < NS * UNITS; i += 288) {
        sn[i] = g_sn[(size_t)b * NS * UNITS + i];
        sd[i] = g_sd[(size_t)b * NS * UNITS + i];
    }
    if (tid < UNITS) {
        v[tid] = 0.f;
        cmt[tid] = g_cmt[tid];
        nc[tid]  = g_nc[tid];
        dc[tid]  = g_dc[tid];
    }
    if (tid < 4) outsum[tid] = 0.f;
    __syncthreads();
    int u = tid % UNITS, g = tid / UNITS;
    for (int s = 0; s < NS; s++) {
        for (int it = 0; it < 6; it++) {
            float accn = 0.f, accd = 0.f;
            #pragma unroll
            for (int j = 0; j < 8; j++) {
                int p = g * 8 + j;
                float4 q = rp[p * UNITS + u];
                float tt = tanhf_a(fmaf(v[p], q.x, q.y));
                accn = fmaf(q.z, tt, accn);
                accd = fmaf(q.w, tt, accd);
            }
            redn[g * UNITS + u] = accn;
            redd[g * UNITS + u] = accd;
            __syncthreads();
            if (tid < UNITS) {
                float a = 0.f, d = 0.f;
                #pragma unroll
                for (int gg = 0; gg < 6; gg++) { a += redn[gg * UNITS + tid]; d += redd[gg * UNITS + tid]; }
                float vv  = v[tid];
                float num = fmaf(cmt[tid], vv, nc[tid]) + a + sn[s * UNITS + tid];
                float den = dc[tid] + d + sd[s * UNITS + tid];
                v[tid] = num * rcpf(den);
            }
            __syncthreads();
        }
        if (tid < 4) outsum[tid] += v[tid];
    }
    __syncthreads();
    if (tid == 0) {
        float p[4];
        #pragma unroll
        for (int m = 0; m < 4; m++)
            p[m] = outsum[m] * (1.f / 48.f) * wout[m] + bout[m];
        #pragma unroll
        for (int j = 0; j < 2; j++) {
            float h = bhead[j];
            #pragma unroll
            for (int m = 0; m < 4; m++) h = fmaf(p[m], whead[m * 2 + j], h);
            out[b * 2 + j] = tanhf(h);
        }
    }
}

// ---------------- launch ----------------
extern "C" void kernel_launch(void* const* d_in, const int* in_sizes, int n_in,
                              void* d_out, int out_size) {
    const float* image   = (const float*)d_in[0];
    const float* rel_pos = (const float*)d_in[1];
    const float* w0 = (const float*)d_in[2];
    const float* b0 = (const float*)d_in[3];
    const float* w1 = (const float*)d_in[4];
    const float* b1 = (const float*)d_in[5];
    const float* w2 = (const float*)d_in[6];
    const float* b2 = (const float*)d_in[7];
    const float* input_w = (const float*)d_in[8];
    const float* input_b = (const float*)d_in[9];
    const float* gleak = (const float*)d_in[10];
    const float* vleak = (const float*)d_in[11];
    const float* cm    = (const float*)d_in[12];
    const float* sigma = (const float*)d_in[13];
    const float* mu    = (const float*)d_in[14];
    const float* w_syn = (const float*)d_in[15];
    const float* erev  = (const float*)d_in[16];
    const float* s_sigma = (const float*)d_in[17];
    const float* s_mu    = (const float*)d_in[18];
    const float* s_w     = (const float*)d_in[19];
    const float* s_erev  = (const float*)d_in[20];
    const float* w_out = (const float*)d_in[21];
    const float* b_out = (const float*)d_in[22];
    const float* w_head = (const float*)d_in[23];
    const float* b_head = (const float*)d_in[24];
    const int* syn_mask  = (const int*)d_in[25];
    const int* sens_mask = (const int*)d_in[26];
    float* out = (float*)d_out;

    const int SM_CONV1 = (C0P + W1SZ) * 4;                          // 179712
    const int SM_CONV2 = (C1P + W2SZ) * 4;                          // 124416
    const int SM_SENS  = SCHUNK * UNITS * 16 + SIMG * SENS * 4;
    const int SM_LTC   = (9216 + 2304 + 2304 + 48 + 288 + 288 + 48 + 48 + 48 + 4) * 4;
    cudaFuncSetAttribute(k_conv1, cudaFuncAttributeMaxDynamicSharedMemorySize, SM_CONV1);
    cudaFuncSetAttribute(k_conv2, cudaFuncAttributeMaxDynamicSharedMemorySize, SM_CONV2);
    cudaFuncSetAttribute(k_sens,  cudaFuncAttributeMaxDynamicSharedMemorySize, SM_SENS);
    cudaFuncSetAttribute(k_ltc,   cudaFuncAttributeMaxDynamicSharedMemorySize, SM_LTC);

    k_prep_sens<<<(SENS * UNITS + 255) / 256, 256>>>(input_w, input_b, s_sigma, s_mu,
                                                     s_w, s_erev, sens_mask);
    k_prep_rec<<<(UNITS * UNITS + 255) / 256, 256>>>(sigma, mu, w_syn, erev, syn_mask);
    k_prep_const<<<UNITS, 256>>>(gleak, vleak, cm);
    k_conv0<<<NIMG, 512>>>(image, w0, b0);
    k_conv1<<<NIMG, 352, SM_CONV1>>>(w1, b1);
    k_conv2<<<NIMG, 320, SM_CONV2>>>(w2, b2, rel_pos);
    k_sens<<<NIMG / SIMG, SIMG * UNITS, SM_SENS>>>();
    k_ltc<<<NB, 288, SM_LTC>>>(w_out, b_out, w_head, b_head, out);
}

// round 6
// speedup vs baseline: 1.5084x; 1.1796x over previous
#include <cuda_runtime.h>
#include <math.h>

typedef unsigned long long ull;

// ---------------- problem constants ----------------
#define NIMG   1536            // B*S
#define UNITS  48
#define SENS   1283
#define NB     32
#define NS     48
#define H0 48
#define W0 72

// sc0 interleaved ic-pair layout: [icp=16][row<=23 (alloc 24)][pos 0..35][2]
// row stride 92 floats (368B): 368 mod 128 = 112 -> 8 distinct bank offsets over rows,
// no intra-row swizzle, rows cannot overlap (72 data floats <= 92).
#define PSTR 92
#define PLN  (24*PSTR)          // 2208 floats per plane
#define SC0SZ (16*PLN)          // 35328 floats
#define W1PSZ (64*16*9*2)       // 18432 floats (oc, icp, j) -> pair
#define W2PSZ (32*32*9*2)       // 18432 floats
#define C1PSZ (32*11*18*2)      // 12672 floats/img: [ocq][y][x(pad18)][2]

// ---------------- device scratch ----------------
__device__ float  g_c1p[(size_t)NIMG * C1PSZ];      // conv1 out, pair-interleaved
__device__ float  g_x [(size_t)NIMG * SENS];
__device__ float  g_sn[(size_t)NIMG * UNITS];
__device__ float  g_sd[(size_t)NIMG * UNITS];
__device__ float4 g_sp[SENS * UNITS];
__device__ float4 g_rp[UNITS * UNITS];
__device__ float  g_skn[UNITS], g_skd[UNITS];
__device__ float  g_nc[UNITS], g_dc[UNITS], g_cmt[UNITS];
__device__ float  g_w1p[W1PSZ];
__device__ float  g_w2p[W2PSZ];

// ---------------- fast math helpers ----------------
__device__ __forceinline__ float rcpf(float x) {
    float y; asm("rcp.approx.f32 %0, %1;" : "=f"(y) : "f"(x)); return y;
}
__device__ __forceinline__ float tanhf_a(float x) {
    float y; asm("tanh.approx.f32 %0, %1;" : "=f"(y) : "f"(x)); return y;
}
__device__ __forceinline__ ull ffma2(ull a, ull b, ull c) {
    ull d; asm("fma.rn.f32x2 %0, %1, %2, %3;" : "=l"(d) : "l"(a), "l"(b), "l"(c));
    return d;
}
__device__ __forceinline__ float2 unpack2(ull v) {
    float2 r; asm("mov.b64 {%0, %1}, %2;" : "=f"(r.x), "=f"(r.y) : "l"(v));
    return r;
}

// ---------------- prep kernels ----------------
__global__ void k_prep_sens(const float* __restrict__ iw, const float* __restrict__ ib,
                            const float* __restrict__ ssig, const float* __restrict__ smu,
                            const float* __restrict__ sw, const float* __restrict__ serev,
                            const int* __restrict__ smask) {
    int idx = blockIdx.x * blockDim.x + threadIdx.x;
    if (idx >= SENS * UNITS) return;
    int k = idx / UNITS;
    float sg = ssig[idx], m = smu[idx];
    float w  = sw[idx] * (float)smask[idx];
    float A = 0.5f * sg * iw[k];
    float C = 0.5f * sg * (ib[k] - m);
    g_sp[idx] = make_float4(A, C, 0.5f * w * serev[idx], 0.5f * w);
}

__global__ void k_prep_rec(const float* __restrict__ sigma, const float* __restrict__ mu,
                           const float* __restrict__ wsyn, const float* __restrict__ erev,
                           const int* __restrict__ mask) {
    int idx = blockIdx.x * blockDim.x + threadIdx.x;
    if (idx >= UNITS * UNITS) return;
    float sg = sigma[idx], m = mu[idx];
    float w  = wsyn[idx] * (float)mask[idx];
    g_rp[idx] = make_float4(0.5f * sg, -0.5f * sg * m, 0.5f * w * erev[idx], 0.5f * w);
}

__global__ void __launch_bounds__(256) k_prep_const(const float* __restrict__ gleak,
                                                    const float* __restrict__ vleak,
                                                    const float* __restrict__ cm) {
    int u = blockIdx.x, tid = threadIdx.x;
    float kn = 0.f, kd = 0.f;
    for (int k = tid; k < SENS; k += 256) {
        float4 p = g_sp[k * UNITS + u];
        kn += p.z; kd += p.w;
    }
    #pragma unroll
    for (int o = 16; o > 0; o >>= 1) {
        kn += __shfl_xor_sync(0xffffffff, kn, o);
        kd += __shfl_xor_sync(0xffffffff, kd, o);
    }
    __shared__ float swn[8], swd[8];
    if ((tid & 31) == 0) { swn[tid >> 5] = kn; swd[tid >> 5] = kd; }
    __syncthreads();
    if (tid == 0) {
        float tn = 0.f, td = 0.f;
        #pragma unroll
        for (int i = 0; i < 8; i++) { tn += swn[i]; td += swd[i]; }
        g_skn[u] = tn; g_skd[u] = td;
        float rn = 0.f, rd = 0.f;
        for (int p = 0; p < UNITS; p++) { float4 q = g_rp[p * UNITS + u]; rn += q.z; rd += q.w; }
        float cmt = cm[u] * 6.f;
        g_cmt[u] = cmt;
        g_nc[u] = gleak[u] * vleak[u] + rn;
        g_dc[u] = cmt + gleak[u] + rd + 1e-8f;
    }
}

// pack conv weights into ic-pair float2
__global__ void k_prep_w1p(const float* __restrict__ w1) {
    int idx = blockIdx.x * blockDim.x + threadIdx.x;       // over 64*16*9
    if (idx >= 64 * 16 * 9) return;
    int oc = idx / 144, rem = idx % 144, icp = rem / 9, j = rem % 9;
    g_w1p[idx * 2 + 0] = w1[(oc * 32 + 2 * icp) * 9 + j];
    g_w1p[idx * 2 + 1] = w1[(oc * 32 + 2 * icp + 1) * 9 + j];
}
__global__ void k_prep_w2p(const float* __restrict__ w2) {
    int idx = blockIdx.x * blockDim.x + threadIdx.x;       // over 32*32*9
    if (idx >= 32 * 32 * 9) return;
    int oc = idx / 288, rem = idx % 288, icp = rem / 9, j = rem % 9;
    g_w2p[idx * 2 + 0] = w2[(oc * 64 + 2 * icp) * 9 + j];
    g_w2p[idx * 2 + 1] = w2[(oc * 64 + 2 * icp + 1) * 9 + j];
}

// ---------------- kernel A: fused conv0 (1->32) + conv1 (32->64, FFMA2) -----------
// 352 threads; smem: [simg 3456][sw0 288][sw1p 18432][sc0 35328] = 230016B
__global__ void __launch_bounds__(352) k_cnn01(const float* __restrict__ image,
                                               const float* __restrict__ w0,
                                               const float* __restrict__ b0,
                                               const float* __restrict__ b1) {
    extern __shared__ float sm[];
    float* simg = sm;                        // 3456
    float* sw0  = sm + 3456;                 // 288
    float* sw1p = sm + 3744;                 // 18432
    float* sc0  = sm + 3744 + W1PSZ;         // 35328
    int img = blockIdx.x, tid = threadIdx.x;

    {   // stage image + weights
        const float4* src = (const float4*)(image + (size_t)img * (H0 * W0));
        float4* d = (float4*)simg;
        for (int i = tid; i < (H0 * W0) / 4; i += 352) d[i] = src[i];
        for (int i = tid; i < 288; i += 352) sw0[i] = w0[i];
        const float4* ws = (const float4*)g_w1p;
        float4* dw = (float4*)sw1p;
        for (int i = tid; i < W1PSZ / 4; i += 352) dw[i] = ws[i];
    }
    __syncthreads();

    // ---- conv0 phase: warp per (icp, oy); lane = ox ----
    {
        int wid = tid >> 5, lane = tid & 31;
        for (int task = wid; task < 368; task += 11) {
            int icp = task / 23, oy = task % 23;
            float we[9], wo[9];
            #pragma unroll
            for (int j = 0; j < 9; j++) {
                we[j] = sw0[(2 * icp) * 9 + j];
                wo[j] = sw0[(2 * icp + 1) * 9 + j];
            }
            float be = __ldg(&b0[2 * icp]), bo = __ldg(&b0[2 * icp + 1]);
            float2* dst = (float2*)&sc0[icp * PLN + oy * PSTR];
            {   // ox = lane (0..31)
                float ae = be, ao = bo;
                #pragma unroll
                for (int ky = 0; ky < 3; ky++) {
                    const float* row = &simg[(2 * oy + ky) * W0 + 2 * lane];
                    #pragma unroll
                    for (int kx = 0; kx < 3; kx++) {
                        float r = row[kx];
                        ae = fmaf(we[ky * 3 + kx], r, ae);
                        ao = fmaf(wo[ky * 3 + kx], r, ao);
                    }
                }
                dst[lane] = make_float2(fmaxf(ae, 0.f), fmaxf(ao, 0.f));
            }
            if (lane < 4) {   // ox 32..34 + zero pad pos 35
                int ox = 32 + lane;
                float ae = be, ao = bo;
                if (lane < 3) {
                    #pragma unroll
                    for (int ky = 0; ky < 3; ky++) {
                        const float* row = &simg[(2 * oy + ky) * W0 + 2 * ox];
                        #pragma unroll
                        for (int kx = 0; kx < 3; kx++) {
                            float r = row[kx];
                            ae = fmaf(we[ky * 3 + kx], r, ae);
                            ao = fmaf(wo[ky * 3 + kx], r, ao);
                        }
                    }
                    dst[ox] = make_float2(fmaxf(ae, 0.f), fmaxf(ao, 0.f));
                } else {
                    dst[35] = make_float2(0.f, 0.f);
                }
            }
        }
    }
    __syncthreads();

    // ---- conv1 phase: thread = (oc pair, oy); packed f32x2 over ic pairs ----
    int ocq = tid / 11;          // 0..31
    int oy  = tid % 11;
    int oc0 = 2 * ocq;
    ull acc0[17], acc1[17];
    #pragma unroll
    for (int o = 0; o < 17; o++) { acc0[o] = 0ull; acc1[o] = 0ull; }

    #pragma unroll 1
    for (int icp = 0; icp < 16; icp++) {
        const ull* wp0 = (const ull*)&sw1p[(oc0 * 16 + icp) * 18];
        const ull* wp1 = (const ull*)&sw1p[((oc0 + 1) * 16 + icp) * 18];
        #pragma unroll
        for (int ky = 0; ky < 3; ky++) {
            int r = 2 * oy + ky;
            const float* rb = &sc0[icp * PLN + r * PSTR];
            ull w0k[3], w1k[3];
            #pragma unroll
            for (int kx = 0; kx < 3; kx++) { w0k[kx] = wp0[3 * ky + kx]; w1k[kx] = wp1[3 * ky + kx]; }
            {   // chunk A: positions 0..19 -> outputs 0..8
                ull tA[20];
                const ulonglong2* pa = (const ulonglong2*)rb;
                #pragma unroll
                for (int j = 0; j < 10; j++) { ulonglong2 v = pa[j]; tA[2 * j] = v.x; tA[2 * j + 1] = v.y; }
                #pragma unroll
                for (int kx = 0; kx < 3; kx++) {
                    #pragma unroll
                    for (int o = 0; o < 9; o++) {
                        acc0[o] = ffma2(w0k[kx], tA[2 * o + kx], acc0[o]);
                        acc1[o] = ffma2(w1k[kx], tA[2 * o + kx], acc1[o]);
                    }
                }
            }
            {   // chunk B: positions 18..35 -> outputs 9..16
                ull tB[18];
                const ulonglong2* pb = (const ulonglong2*)(rb + 36);
                #pragma unroll
                for (int j = 0; j < 9; j++) { ulonglong2 v = pb[j]; tB[2 * j] = v.x; tB[2 * j + 1] = v.y; }
                #pragma unroll
                for (int kx = 0; kx < 3; kx++) {
                    #pragma unroll
                    for (int o = 9; o < 17; o++) {
                        acc0[o] = ffma2(w0k[kx], tB[2 * o + kx - 18], acc0[o]);
                        acc1[o] = ffma2(w1k[kx], tB[2 * o + kx - 18], acc1[o]);
                    }
                }
            }
        }
    }
    // epilogue: reduce pair halves, bias, relu, write interleaved (oc even, oc odd)
    float bb0 = __ldg(&b1[oc0]), bb1 = __ldg(&b1[oc0 + 1]);
    float2* outp = (float2*)&g_c1p[(size_t)img * C1PSZ + (ocq * 11 + oy) * 36];
    #pragma unroll
    for (int o = 0; o < 17; o++) {
        float2 e = unpack2(acc0[o]);
        float2 f = unpack2(acc1[o]);
        outp[o] = make_float2(fmaxf(e.x + e.y + bb0, 0.f), fmaxf(f.x + f.y + bb1, 0.f));
    }
    outp[17] = make_float2(0.f, 0.f);   // pad position
}

// ---------------- conv2: 64->32, pair-interleaved input, FFMA2 ----------------
// 320 threads = 32 oc * 5 oy * 2 ox-groups(4)
__global__ void __launch_bounds__(320) k_conv2(const float* __restrict__ b2,
                                               const float* __restrict__ relpos) {
    extern __shared__ float sm2[];
    float* sc1  = sm2;              // 12672
    float* sw2p = sm2 + C1PSZ;      // 18432
    int img = blockIdx.x, tid = threadIdx.x;
    {
        const float4* src = (const float4*)&g_c1p[(size_t)img * C1PSZ];
        float4* d = (float4*)sc1;
        for (int i = tid; i < C1PSZ / 4; i += 320) d[i] = src[i];
        const float4* ws = (const float4*)g_w2p;
        float4* dw = (float4*)sw2p;
        for (int i = tid; i < W2PSZ / 4; i += 320) dw[i] = ws[i];
    }
    __syncthreads();
    int oc = tid / 10;
    int rem = tid % 10;
    int oy = rem / 2;
    int p  = rem % 2;
    ull acc[4];
    #pragma unroll
    for (int o = 0; o < 4; o++) acc[o] = 0ull;
    #pragma unroll 1
    for (int icp = 0; icp < 32; icp++) {
        const ull* wp = (const ull*)&sw2p[(oc * 32 + icp) * 18];
        #pragma unroll
        for (int ky = 0; ky < 3; ky++) {
            int r = 2 * oy + ky;
            const ulonglong2* q = (const ulonglong2*)&sc1[icp * 396 + r * 36 + 16 * p];
            ull t[10];
            #pragma unroll
            for (int j = 0; j < 5; j++) { ulonglong2 v = q[j]; t[2 * j] = v.x; t[2 * j + 1] = v.y; }
            ull wk[3];
            #pragma unroll
            for (int kx = 0; kx < 3; kx++) wk[kx] = wp[3 * ky + kx];
            #pragma unroll
            for (int kx = 0; kx < 3; kx++)
                #pragma unroll
                for (int o = 0; o < 4; o++)
                    acc[o] = ffma2(wk[kx], t[2 * o + kx], acc[o]);
        }
    }
    float bb = __ldg(&b2[oc]);
    float* out = &g_x[(size_t)img * SENS + oc * 40 + oy * 8 + 4 * p];
    #pragma unroll
    for (int o = 0; o < 4; o++) {
        float2 e = unpack2(acc[o]);
        out[o] = fmaxf(e.x + e.y + bb, 0.f);
    }
    if (tid < 3) g_x[(size_t)img * SENS + 1280 + tid] = relpos[(size_t)img * 3 + tid];
}

// ---------------- sensory synapse precompute: 12 images/block ----------------
#define SCHUNK 96
#define SIMG   12
__global__ void __launch_bounds__(SIMG * UNITS) k_sens() {
    extern __shared__ float sm3[];
    float4* sp = (float4*)sm3;
    float*  xs = sm3 + SCHUNK * UNITS * 4;
    int tid = threadIdx.x;
    int img0 = blockIdx.x * SIMG;
    for (int i = tid; i < SIMG * SENS; i += SIMG * UNITS)
        xs[i] = g_x[(size_t)img0 * SENS + i];
    int u = tid % UNITS, t = tid / UNITS;
    float accn = 0.f, accd = 0.f;
    const float* xrow = &xs[t * SENS];
    for (int k0 = 0; k0 < SENS; k0 += SCHUNK) {
        int C = min(SCHUNK, SENS - k0);
        __syncthreads();
        for (int i = tid; i < C * UNITS; i += SIMG * UNITS) sp[i] = g_sp[k0 * UNITS + i];
        __syncthreads();
        #pragma unroll 4
        for (int kk = 0; kk < C; kk++) {
            float4 p = sp[kk * UNITS + u];
            float xv = xrow[k0 + kk];
            float tt = tanhf_a(fmaf(xv, p.x, p.y));
            accn = fmaf(p.z, tt, accn);
            accd = fmaf(p.w, tt, accd);
        }
    }
    g_sn[(size_t)(img0 + t) * UNITS + u] = g_skn[u] + accn;
    g_sd[(size_t)(img0 + t) * UNITS + u] = g_skd[u] + accd;
}

// ---------------- LTC recurrence + pooling + head ----------------
__global__ void __launch_bounds__(288) k_ltc(const float* __restrict__ wout,
                                             const float* __restrict__ bout,
                                             const float* __restrict__ whead,
                                             const float* __restrict__ bhead,
                                             float* __restrict__ out) {
    extern __shared__ float sm4[];
    float4* rp   = (float4*)sm4;
    float*  sn   = sm4 + 9216;
    float*  sd   = sn + 2304;
    float*  v    = sd + 2304;
    float*  redn = v + 48;
    float*  redd = redn + 288;
    float*  cmt  = redd + 288;
    float*  nc   = cmt + 48;
    float*  dc   = nc + 48;
    float*  outsum = dc + 48;
    int b = blockIdx.x, tid = threadIdx.x;
    for (int i = tid; i < UNITS * UNITS; i += 288) rp[i] = g_rp[i];
    for (int i = tid; i < NS * UNITS; i += 288) {
        sn[i] = g_sn[(size_t)b * NS * UNITS + i];
        sd[i] = g_sd[(size_t)b * NS * UNITS + i];
    }
    if (tid < UNITS) {
        v[tid] = 0.f;
        cmt[tid] = g_cmt[tid];
        nc[tid]  = g_nc[tid];
        dc[tid]  = g_dc[tid];
    }
    if (tid < 4) outsum[tid] = 0.f;
    __syncthreads();
    int u = tid % UNITS, g = tid / UNITS;
    for (int s = 0; s < NS; s++) {
        for (int it = 0; it < 6; it++) {
            float accn = 0.f, accd = 0.f;
            #pragma unroll
            for (int j = 0; j < 8; j++) {
                int p = g * 8 + j;
                float4 q = rp[p * UNITS + u];
                float tt = tanhf_a(fmaf(v[p], q.x, q.y));
                accn = fmaf(q.z, tt, accn);
                accd = fmaf(q.w, tt, accd);
            }
            redn[g * UNITS + u] = accn;
            redd[g * UNITS + u] = accd;
            __syncthreads();
            if (tid < UNITS) {
                float a = 0.f, d = 0.f;
                #pragma unroll
                for (int gg = 0; gg < 6; gg++) { a += redn[gg * UNITS + tid]; d += redd[gg * UNITS + tid]; }
                float vv  = v[tid];
                float num = fmaf(cmt[tid], vv, nc[tid]) + a + sn[s * UNITS + tid];
                float den = dc[tid] + d + sd[s * UNITS + tid];
                v[tid] = num * rcpf(den);
            }
            __syncthreads();
        }
        if (tid < 4) outsum[tid] += v[tid];
    }
    __syncthreads();
    if (tid == 0) {
        float p[4];
        #pragma unroll
        for (int m = 0; m < 4; m++)
            p[m] = outsum[m] * (1.f / 48.f) * wout[m] + bout[m];
        #pragma unroll
        for (int j = 0; j < 2; j++) {
            float h = bhead[j];
            #pragma unroll
            for (int m = 0; m < 4; m++) h = fmaf(p[m], whead[m * 2 + j], h);
            out[b * 2 + j] = tanhf(h);
        }
    }
}

// ---------------- launch ----------------
extern "C" void kernel_launch(void* const* d_in, const int* in_sizes, int n_in,
                              void* d_out, int out_size) {
    const float* image   = (const float*)d_in[0];
    const float* rel_pos = (const float*)d_in[1];
    const float* w0 = (const float*)d_in[2];
    const float* b0 = (const float*)d_in[3];
    const float* w1 = (const float*)d_in[4];
    const float* b1 = (const float*)d_in[5];
    const float* w2 = (const float*)d_in[6];
    const float* b2 = (const float*)d_in[7];
    const float* input_w = (const float*)d_in[8];
    const float* input_b = (const float*)d_in[9];
    const float* gleak = (const float*)d_in[10];
    const float* vleak = (const float*)d_in[11];
    const float* cm    = (const float*)d_in[12];
    const float* sigma = (const float*)d_in[13];
    const float* mu    = (const float*)d_in[14];
    const float* w_syn = (const float*)d_in[15];
    const float* erev  = (const float*)d_in[16];
    const float* s_sigma = (const float*)d_in[17];
    const float* s_mu    = (const float*)d_in[18];
    const float* s_w     = (const float*)d_in[19];
    const float* s_erev  = (const float*)d_in[20];
    const float* w_out = (const float*)d_in[21];
    const float* b_out = (const float*)d_in[22];
    const float* w_head = (const float*)d_in[23];
    const float* b_head = (const float*)d_in[24];
    const int* syn_mask  = (const int*)d_in[25];
    const int* sens_mask = (const int*)d_in[26];
    float* out = (float*)d_out;

    const int SM_A     = (3456 + 288 + W1PSZ + SC0SZ) * 4;      // 230016
    const int SM_CONV2 = (C1PSZ + W2PSZ) * 4;                   // 124416
    const int SM_SENS  = SCHUNK * UNITS * 16 + SIMG * SENS * 4;
    const int SM_LTC   = (9216 + 2304 + 2304 + 48 + 288 + 288 + 48 + 48 + 48 + 4) * 4;
    cudaFuncSetAttribute(k_cnn01, cudaFuncAttributeMaxDynamicSharedMemorySize, SM_A);
    cudaFuncSetAttribute(k_conv2, cudaFuncAttributeMaxDynamicSharedMemorySize, SM_CONV2);
    cudaFuncSetAttribute(k_sens,  cudaFuncAttributeMaxDynamicSharedMemorySize, SM_SENS);
    cudaFuncSetAttribute(k_ltc,   cudaFuncAttributeMaxDynamicSharedMemorySize, SM_LTC);

    k_prep_sens<<<(SENS * UNITS + 255) / 256, 256>>>(input_w, input_b, s_sigma, s_mu,
                                                     s_w, s_erev, sens_mask);
    k_prep_rec<<<(UNITS * UNITS + 255) / 256, 256>>>(sigma, mu, w_syn, erev, syn_mask);
    k_prep_const<<<UNITS, 256>>>(gleak, vleak, cm);
    k_prep_w1p<<<(64 * 16 * 9 + 255) / 256, 256>>>(w1);
    k_prep_w2p<<<(32 * 32 * 9 + 255) / 256, 256>>>(w2);
    k_cnn01<<<NIMG, 352, SM_A>>>(image, w0, b0, b1);
    k_conv2<<<NIMG, 320, SM_CONV2>>>(b2, rel_pos);
    k_sens<<<NIMG / SIMG, SIMG * UNITS, SM_SENS>>>();
    k_ltc<<<NB, 288, SM_LTC>>>(w_out, b_out, w_head, b_head, out);
}

// round 7
// speedup vs baseline: 2.5898x; 1.7169x over previous
#include <cuda_runtime.h>
#include <math.h>

typedef unsigned long long ull;

// ---------------- problem constants ----------------
#define NIMG   1536            // B*S
#define UNITS  48
#define SENS   1283
#define NB     32
#define NS     48
#define H0 48
#define W0 72

// sc0 interleaved ic-pair layout: [icp=16][row<=23 (alloc 24)][pos 0..35][2]
#define PSTR 92
#define PLN  (24*PSTR)          // 2208 floats per plane
#define SC0SZ (16*PLN)          // 35328 floats
#define W1PSZ (16*9*64*2)       // 18432 floats: [icp][j][oc] ull pairs
#define W2PSZ (32*9*32*2)       // 18432 floats: [icp][j][oc] ull
#define C1PSZ (32*11*18*2)      // 12672 floats/img: [ocq][y][x(pad18)][2]

// ---------------- device scratch ----------------
__device__ float  g_c1p[(size_t)NIMG * C1PSZ];      // conv1 out, pair-interleaved
__device__ float  g_x [(size_t)NIMG * SENS];
__device__ float  g_sn[(size_t)NIMG * UNITS];
__device__ float  g_sd[(size_t)NIMG * UNITS];
__device__ float4 g_sp[SENS * UNITS];
__device__ float4 g_rp[UNITS * UNITS];
__device__ float  g_skn[UNITS], g_skd[UNITS];
__device__ float  g_nc[UNITS], g_dc[UNITS], g_cmt[UNITS];
__device__ float  g_w1p[W1PSZ];
__device__ float  g_w2p[W2PSZ];

// ---------------- fast math helpers ----------------
__device__ __forceinline__ float rcpf(float x) {
    float y; asm("rcp.approx.f32 %0, %1;" : "=f"(y) : "f"(x)); return y;
}
__device__ __forceinline__ float tanhf_a(float x) {
    float y; asm("tanh.approx.f32 %0, %1;" : "=f"(y) : "f"(x)); return y;
}
__device__ __forceinline__ ull ffma2(ull a, ull b, ull c) {
    ull d; asm("fma.rn.f32x2 %0, %1, %2, %3;" : "=l"(d) : "l"(a), "l"(b), "l"(c));
    return d;
}
__device__ __forceinline__ float2 unpack2(ull v) {
    float2 r; asm("mov.b64 {%0, %1}, %2;" : "=f"(r.x), "=f"(r.y) : "l"(v));
    return r;
}
__device__ __forceinline__ ull pack2(float lo, float hi) {
    ull v; asm("mov.b64 %0, {%1, %2};" : "=l"(v) : "f"(lo), "f"(hi));
    return v;
}

// ---------------- prep kernels ----------------
__global__ void k_prep_sens(const float* __restrict__ iw, const float* __restrict__ ib,
                            const float* __restrict__ ssig, const float* __restrict__ smu,
                            const float* __restrict__ sw, const float* __restrict__ serev,
                            const int* __restrict__ smask) {
    int idx = blockIdx.x * blockDim.x + threadIdx.x;
    if (idx >= SENS * UNITS) return;
    int k = idx / UNITS;
    float sg = ssig[idx], m = smu[idx];
    float w  = sw[idx] * (float)smask[idx];
    float A = 0.5f * sg * iw[k];
    float C = 0.5f * sg * (ib[k] - m);
    g_sp[idx] = make_float4(A, C, 0.5f * w * serev[idx], 0.5f * w);
}

__global__ void k_prep_rec(const float* __restrict__ sigma, const float* __restrict__ mu,
                           const float* __restrict__ wsyn, const float* __restrict__ erev,
                           const int* __restrict__ mask) {
    int idx = blockIdx.x * blockDim.x + threadIdx.x;
    if (idx >= UNITS * UNITS) return;
    float sg = sigma[idx], m = mu[idx];
    float w  = wsyn[idx] * (float)mask[idx];
    g_rp[idx] = make_float4(0.5f * sg, -0.5f * sg * m, 0.5f * w * erev[idx], 0.5f * w);
}

__global__ void __launch_bounds__(256) k_prep_const(const float* __restrict__ gleak,
                                                    const float* __restrict__ vleak,
                                                    const float* __restrict__ cm) {
    int u = blockIdx.x, tid = threadIdx.x;
    float kn = 0.f, kd = 0.f;
    for (int k = tid; k < SENS; k += 256) {
        float4 p = g_sp[k * UNITS + u];
        kn += p.z; kd += p.w;
    }
    #pragma unroll
    for (int o = 16; o > 0; o >>= 1) {
        kn += __shfl_xor_sync(0xffffffff, kn, o);
        kd += __shfl_xor_sync(0xffffffff, kd, o);
    }
    __shared__ float swn[8], swd[8];
    if ((tid & 31) == 0) { swn[tid >> 5] = kn; swd[tid >> 5] = kd; }
    __syncthreads();
    if (tid == 0) {
        float tn = 0.f, td = 0.f;
        #pragma unroll
        for (int i = 0; i < 8; i++) { tn += swn[i]; td += swd[i]; }
        g_skn[u] = tn; g_skd[u] = td;
        float rn = 0.f, rd = 0.f;
        for (int p = 0; p < UNITS; p++) { float4 q = g_rp[p * UNITS + u]; rn += q.z; rd += q.w; }
        float cmt = cm[u] * 6.f;
        g_cmt[u] = cmt;
        g_nc[u] = gleak[u] * vleak[u] + rn;
        g_dc[u] = cmt + gleak[u] + rd + 1e-8f;
    }
}

// pack conv1 weights oc-major: g_w1p ull[(icp*9 + j)*64 + oc] = (w[2icp], w[2icp+1])
__global__ void k_prep_w1p(const float* __restrict__ w1) {
    int idx = blockIdx.x * blockDim.x + threadIdx.x;       // over 16*9*64
    if (idx >= 16 * 9 * 64) return;
    int icp = idx / 576, rem = idx % 576, j = rem / 64, oc = rem % 64;
    g_w1p[idx * 2 + 0] = w1[(oc * 32 + 2 * icp) * 9 + j];
    g_w1p[idx * 2 + 1] = w1[(oc * 32 + 2 * icp + 1) * 9 + j];
}
// pack conv2 weights oc-major: g_w2p ull[(icp*9 + j)*32 + oc]
__global__ void k_prep_w2p(const float* __restrict__ w2) {
    int idx = blockIdx.x * blockDim.x + threadIdx.x;       // over 32*9*32
    if (idx >= 32 * 9 * 32) return;
    int icp = idx / 288, rem = idx % 288, j = rem / 32, oc = rem % 32;
    g_w2p[idx * 2 + 0] = w2[(oc * 64 + 2 * icp) * 9 + j];
    g_w2p[idx * 2 + 1] = w2[(oc * 64 + 2 * icp + 1) * 9 + j];
}

// ---------------- kernel A: fused conv0 (1->32) + conv1 (32->64, FFMA2) -----------
// 352 threads; conv1 mapping: warp = oy (11 warps), lane = ocq -> row loads broadcast,
// weight loads coalesced. smem 230016B.
__global__ void __launch_bounds__(352) k_cnn01(const float* __restrict__ image,
                                               const float* __restrict__ w0,
                                               const float* __restrict__ b0,
                                               const float* __restrict__ b1) {
    extern __shared__ float sm[];
    float* simg = sm;                        // 3456
    float* sw0  = sm + 3456;                 // 288
    float* sw1p = sm + 3744;                 // 18432
    float* sc0  = sm + 3744 + W1PSZ;         // 35328
    int img = blockIdx.x, tid = threadIdx.x;

    {   // stage image + weights
        const float4* src = (const float4*)(image + (size_t)img * (H0 * W0));
        float4* d = (float4*)simg;
        for (int i = tid; i < (H0 * W0) / 4; i += 352) d[i] = src[i];
        for (int i = tid; i < 288; i += 352) sw0[i] = w0[i];
        const float4* ws = (const float4*)g_w1p;
        float4* dw = (float4*)sw1p;
        for (int i = tid; i < W1PSZ / 4; i += 352) dw[i] = ws[i];
    }
    __syncthreads();

    // ---- conv0 phase: warp per (icp, oy); lane = ox ----
    {
        int wid = tid >> 5, lane = tid & 31;
        for (int task = wid; task < 368; task += 11) {
            int icp = task / 23, oy = task % 23;
            float we[9], wo[9];
            #pragma unroll
            for (int j = 0; j < 9; j++) {
                we[j] = sw0[(2 * icp) * 9 + j];
                wo[j] = sw0[(2 * icp + 1) * 9 + j];
            }
            float be = __ldg(&b0[2 * icp]), bo = __ldg(&b0[2 * icp + 1]);
            float2* dst = (float2*)&sc0[icp * PLN + oy * PSTR];
            {   // ox = lane (0..31)
                float ae = be, ao = bo;
                #pragma unroll
                for (int ky = 0; ky < 3; ky++) {
                    const float* row = &simg[(2 * oy + ky) * W0 + 2 * lane];
                    #pragma unroll
                    for (int kx = 0; kx < 3; kx++) {
                        float r = row[kx];
                        ae = fmaf(we[ky * 3 + kx], r, ae);
                        ao = fmaf(wo[ky * 3 + kx], r, ao);
                    }
                }
                dst[lane] = make_float2(fmaxf(ae, 0.f), fmaxf(ao, 0.f));
            }
            if (lane < 4) {   // ox 32..34 + zero pad pos 35
                int ox = 32 + lane;
                float ae = be, ao = bo;
                if (lane < 3) {
                    #pragma unroll
                    for (int ky = 0; ky < 3; ky++) {
                        const float* row = &simg[(2 * oy + ky) * W0 + 2 * ox];
                        #pragma unroll
                        for (int kx = 0; kx < 3; kx++) {
                            float r = row[kx];
                            ae = fmaf(we[ky * 3 + kx], r, ae);
                            ao = fmaf(wo[ky * 3 + kx], r, ao);
                        }
                    }
                    dst[ox] = make_float2(fmaxf(ae, 0.f), fmaxf(ao, 0.f));
                } else {
                    dst[35] = make_float2(0.f, 0.f);
                }
            }
        }
    }
    __syncthreads();

    // ---- conv1 phase: warp = oy, lane = ocq ----
    int oy  = tid >> 5;          // 0..10
    int ocq = tid & 31;          // 0..31
    int oc0 = 2 * ocq;
    const ull* swq = (const ull*)sw1p;
    ull acc0[17], acc1[17];
    #pragma unroll
    for (int o = 0; o < 17; o++) { acc0[o] = 0ull; acc1[o] = 0ull; }

    #pragma unroll 1
    for (int icp = 0; icp < 16; icp++) {
        #pragma unroll
        for (int ky = 0; ky < 3; ky++) {
            int r = 2 * oy + ky;
            const float* rb = &sc0[icp * PLN + r * PSTR];
            // coalesced weight loads: (icp*9 + ky*3 + kx)*64 + 2*ocq
            ulonglong2 wv[3];
            #pragma unroll
            for (int kx = 0; kx < 3; kx++)
                wv[kx] = *(const ulonglong2*)&swq[(icp * 9 + ky * 3 + kx) * 64 + oc0];
            {   // chunk A: positions 0..19 -> outputs 0..8 (broadcast row loads)
                ull tA[20];
                const ulonglong2* pa = (const ulonglong2*)rb;
                #pragma unroll
                for (int j = 0; j < 10; j++) { ulonglong2 v = pa[j]; tA[2 * j] = v.x; tA[2 * j + 1] = v.y; }
                #pragma unroll
                for (int kx = 0; kx < 3; kx++) {
                    #pragma unroll
                    for (int o = 0; o < 9; o++) {
                        acc0[o] = ffma2(wv[kx].x, tA[2 * o + kx], acc0[o]);
                        acc1[o] = ffma2(wv[kx].y, tA[2 * o + kx], acc1[o]);
                    }
                }
            }
            {   // chunk B: positions 18..35 -> outputs 9..16
                ull tB[18];
                const ulonglong2* pb = (const ulonglong2*)(rb + 36);
                #pragma unroll
                for (int j = 0; j < 9; j++) { ulonglong2 v = pb[j]; tB[2 * j] = v.x; tB[2 * j + 1] = v.y; }
                #pragma unroll
                for (int kx = 0; kx < 3; kx++) {
                    #pragma unroll
                    for (int o = 9; o < 17; o++) {
                        acc0[o] = ffma2(wv[kx].x, tB[2 * o + kx - 18], acc0[o]);
                        acc1[o] = ffma2(wv[kx].y, tB[2 * o + kx - 18], acc1[o]);
                    }
                }
            }
        }
    }
    // epilogue: reduce pair halves, bias, relu, write interleaved (oc even, oc odd)
    float bb0 = __ldg(&b1[oc0]), bb1 = __ldg(&b1[oc0 + 1]);
    float2* outp = (float2*)&g_c1p[(size_t)img * C1PSZ + (ocq * 11 + oy) * 36];
    #pragma unroll
    for (int o = 0; o < 17; o++) {
        float2 e = unpack2(acc0[o]);
        float2 f = unpack2(acc1[o]);
        outp[o] = make_float2(fmaxf(e.x + e.y + bb0, 0.f), fmaxf(f.x + f.y + bb1, 0.f));
    }
    outp[17] = make_float2(0.f, 0.f);   // pad position
}

// ---------------- conv2: 64->32, pair-interleaved input, FFMA2 ----------------
// 320 threads = 10 warps; warp = (oy, p), lane = oc -> broadcast rows, coalesced weights
__global__ void __launch_bounds__(320) k_conv2(const float* __restrict__ b2,
                                               const float* __restrict__ relpos) {
    extern __shared__ float sm2[];
    float* sc1  = sm2;              // 12672
    float* sw2p = sm2 + C1PSZ;      // 18432
    int img = blockIdx.x, tid = threadIdx.x;
    {
        const float4* src = (const float4*)&g_c1p[(size_t)img * C1PSZ];
        float4* d = (float4*)sc1;
        for (int i = tid; i < C1PSZ / 4; i += 320) d[i] = src[i];
        const float4* ws = (const float4*)g_w2p;
        float4* dw = (float4*)sw2p;
        for (int i = tid; i < W2PSZ / 4; i += 320) dw[i] = ws[i];
    }
    __syncthreads();
    int w  = tid >> 5;          // 0..9
    int oy = w >> 1;            // 0..4
    int p  = w & 1;             // 0..1
    int oc = tid & 31;          // 0..31
    const ull* swq = (const ull*)sw2p;
    ull acc[4];
    #pragma unroll
    for (int o = 0; o < 4; o++) acc[o] = 0ull;
    #pragma unroll 1
    for (int icp = 0; icp < 32; icp++) {
        #pragma unroll
        for (int ky = 0; ky < 3; ky++) {
            int r = 2 * oy + ky;
            const ulonglong2* q = (const ulonglong2*)&sc1[icp * 396 + r * 36 + 16 * p];
            ull t[10];
            #pragma unroll
            for (int j = 0; j < 5; j++) { ulonglong2 v = q[j]; t[2 * j] = v.x; t[2 * j + 1] = v.y; }
            #pragma unroll
            for (int kx = 0; kx < 3; kx++) {
                ull wk = swq[(icp * 9 + ky * 3 + kx) * 32 + oc];
                #pragma unroll
                for (int o = 0; o < 4; o++)
                    acc[o] = ffma2(wk, t[2 * o + kx], acc[o]);
            }
        }
    }
    float bb = __ldg(&b2[oc]);
    float* out = &g_x[(size_t)img * SENS + oc * 40 + oy * 8 + 4 * p];
    #pragma unroll
    for (int o = 0; o < 4; o++) {
        float2 e = unpack2(acc[o]);
        out[o] = fmaxf(e.x + e.y + bb, 0.f);
    }
    if (tid < 3) g_x[(size_t)img * SENS + 1280 + tid] = relpos[(size_t)img * 3 + tid];
}

// ---------------- sensory synapse precompute: 12 images/block ----------------
#define SCHUNK 96
#define SIMG   12
__global__ void __launch_bounds__(SIMG * UNITS) k_sens() {
    extern __shared__ float sm3[];
    float4* sp = (float4*)sm3;
    float*  xs = sm3 + SCHUNK * UNITS * 4;
    int tid = threadIdx.x;
    int img0 = blockIdx.x * SIMG;
    for (int i = tid; i < SIMG * SENS; i += SIMG * UNITS)
        xs[i] = g_x[(size_t)img0 * SENS + i];
    int u = tid % UNITS, t = tid / UNITS;
    float accn = 0.f, accd = 0.f;
    const float* xrow = &xs[t * SENS];
    for (int k0 = 0; k0 < SENS; k0 += SCHUNK) {
        int C = min(SCHUNK, SENS - k0);
        __syncthreads();
        for (int i = tid; i < C * UNITS; i += SIMG * UNITS) sp[i] = g_sp[k0 * UNITS + i];
        __syncthreads();
        #pragma unroll 4
        for (int kk = 0; kk < C; kk++) {
            float4 p = sp[kk * UNITS + u];
            float xv = xrow[k0 + kk];
            float tt = tanhf_a(fmaf(xv, p.x, p.y));
            accn = fmaf(p.z, tt, accn);
            accd = fmaf(p.w, tt, accd);
        }
    }
    g_sn[(size_t)(img0 + t) * UNITS + u] = g_skn[u] + accn;
    g_sd[(size_t)(img0 + t) * UNITS + u] = g_skd[u] + accd;
}

// ---------------- LTC recurrence + pooling + head ----------------
__global__ void __launch_bounds__(288) k_ltc(const float* __restrict__ wout,
                                             const float* __restrict__ bout,
                                             const float* __restrict__ whead,
                                             const float* __restrict__ bhead,
                                             float* __restrict__ out) {
    extern __shared__ float sm4[];
    float4* rp   = (float4*)sm4;
    float*  sn   = sm4 + 9216;
    float*  sd   = sn + 2304;
    float*  v    = sd + 2304;
    float*  redn = v + 48;
    float*  redd = redn + 288;
    float*  cmt  = redd + 288;
    float*  nc   = cmt + 48;
    float*  dc   = nc + 48;
    float*  outsum = dc + 48;
    int b = blockIdx.x, tid = threadIdx.x;
    for (int i = tid; i < UNITS * UNITS; i += 288) rp[i] = g_rp[i];
    for (int i = tid; i < NS * UNITS; i += 288) {
        sn[i] = g_sn[(size_t)b * NS * UNITS + i];
        sd[i] = g_sd[(size_t)b * NS * UNITS + i];
    }
    if (tid < UNITS) {
        v[tid] = 0.f;
        cmt[tid] = g_cmt[tid];
        nc[tid]  = g_nc[tid];
        dc[tid]  = g_dc[tid];
    }
    if (tid < 4) outsum[tid] = 0.f;
    __syncthreads();
    int u = tid % UNITS, g = tid / UNITS;
    for (int s = 0; s < NS; s++) {
        for (int it = 0; it < 6; it++) {
            float accn = 0.f, accd = 0.f;
            #pragma unroll
            for (int j = 0; j < 8; j++) {
                int p = g * 8 + j;
                float4 q = rp[p * UNITS + u];
                float tt = tanhf_a(fmaf(v[p], q.x, q.y));
                accn = fmaf(q.z, tt, accn);
                accd = fmaf(q.w, tt, accd);
            }
            redn[g * UNITS + u] = accn;
            redd[g * UNITS + u] = accd;
            __syncthreads();
            if (tid < UNITS) {
                float a = 0.f, d = 0.f;
                #pragma unroll
                for (int gg = 0; gg < 6; gg++) { a += redn[gg * UNITS + tid]; d += redd[gg * UNITS + tid]; }
                float vv  = v[tid];
                float num = fmaf(cmt[tid], vv, nc[tid]) + a + sn[s * UNITS + tid];
                float den = dc[tid] + d + sd[s * UNITS + tid];
                v[tid] = num * rcpf(den);
            }
            __syncthreads();
        }
        if (tid < 4) outsum[tid] += v[tid];
    }
    __syncthreads();
    if (tid == 0) {
        float p[4];
        #pragma unroll
        for (int m = 0; m < 4; m++)
            p[m] = outsum[m] * (1.f / 48.f) * wout[m] + bout[m];
        #pragma unroll
        for (int j = 0; j < 2; j++) {
            float h = bhead[j];
            #pragma unroll
            for (int m = 0; m < 4; m++) h = fmaf(p[m], whead[m * 2 + j], h);
            out[b * 2 + j] = tanhf(h);
        }
    }
}

// ---------------- launch ----------------
extern "C" void kernel_launch(void* const* d_in, const int* in_sizes, int n_in,
                              void* d_out, int out_size) {
    const float* image   = (const float*)d_in[0];
    const float* rel_pos = (const float*)d_in[1];
    const float* w0 = (const float*)d_in[2];
    const float* b0 = (const float*)d_in[3];
    const float* w1 = (const float*)d_in[4];
    const float* b1 = (const float*)d_in[5];
    const float* w2 = (const float*)d_in[6];
    const float* b2 = (const float*)d_in[7];
    const float* input_w = (const float*)d_in[8];
    const float* input_b = (const float*)d_in[9];
    const float* gleak = (const float*)d_in[10];
    const float* vleak = (const float*)d_in[11];
    const float* cm    = (const float*)d_in[12];
    const float* sigma = (const float*)d_in[13];
    const float* mu    = (const float*)d_in[14];
    const float* w_syn = (const float*)d_in[15];
    const float* erev  = (const float*)d_in[16];
    const float* s_sigma = (const float*)d_in[17];
    const float* s_mu    = (const float*)d_in[18];
    const float* s_w     = (const float*)d_in[19];
    const float* s_erev  = (const float*)d_in[20];
    const float* w_out = (const float*)d_in[21];
    const float* b_out = (const float*)d_in[22];
    const float* w_head = (const float*)d_in[23];
    const float* b_head = (const float*)d_in[24];
    const int* syn_mask  = (const int*)d_in[25];
    const int* sens_mask = (const int*)d_in[26];
    float* out = (float*)d_out;

    const int SM_A     = (3456 + 288 + W1PSZ + SC0SZ) * 4;      // 230016
    const int SM_CONV2 = (C1PSZ + W2PSZ) * 4;                   // 124416
    const int SM_SENS  = SCHUNK * UNITS * 16 + SIMG * SENS * 4;
    const int SM_LTC   = (9216 + 2304 + 2304 + 48 + 288 + 288 + 48 + 48 + 48 + 4) * 4;
    cudaFuncSetAttribute(k_cnn01, cudaFuncAttributeMaxDynamicSharedMemorySize, SM_A);
    cudaFuncSetAttribute(k_conv2, cudaFuncAttributeMaxDynamicSharedMemorySize, SM_CONV2);
    cudaFuncSetAttribute(k_sens,  cudaFuncAttributeMaxDynamicSharedMemorySize, SM_SENS);
    cudaFuncSetAttribute(k_ltc,   cudaFuncAttributeMaxDynamicSharedMemorySize, SM_LTC);

    k_prep_sens<<<(SENS * UNITS + 255) / 256, 256>>>(input_w, input_b, s_sigma, s_mu,
                                                     s_w, s_erev, sens_mask);
    k_prep_rec<<<(UNITS * UNITS + 255) / 256, 256>>>(sigma, mu, w_syn, erev, syn_mask);
    k_prep_const<<<UNITS, 256>>>(gleak, vleak, cm);
    k_prep_w1p<<<(16 * 9 * 64 + 255) / 256, 256>>>(w1);
    k_prep_w2p<<<(32 * 9 * 32 + 255) / 256, 256>>>(w2);
    k_cnn01<<<NIMG, 352, SM_A>>>(image, w0, b0, b1);
    k_conv2<<<NIMG, 320, SM_CONV2>>>(b2, rel_pos);
    k_sens<<<NIMG / SIMG, SIMG * UNITS, SM_SENS>>>();
    k_ltc<<<NB, 288, SM_LTC>>>(w_out, b_out, w_head, b_head, out);
}

// round 8
// speedup vs baseline: 2.8748x; 1.1101x over previous
#include <cuda_runtime.h>
#include <math.h>

typedef unsigned long long ull;

// ---------------- problem constants ----------------
#define NIMG   1536            // B*S
#define UNITS  48
#define SENS   1283
#define NB     32
#define NS     48
#define H0 48
#define W0 72

// sc0 interleaved ic-pair layout: [icp=16][row<=23 (alloc 24)][pos 0..35][2]
#define PSTR 92
#define PLN  (24*PSTR)          // 2208 floats per plane
#define SC0SZ (16*PLN)          // 35328 floats
#define W1PSZ (16*9*64*2)       // 18432 floats: [icp][j][oc] ull pairs
#define W2PSZ (32*9*32*2)       // 18432 floats: [icp][j][oc] ull
#define C1PSZ (32*11*18*2)      // 12672 floats: [ocq][y][x(pad18)][2] (smem only now)

// ---------------- device scratch ----------------
__device__ float  g_x [(size_t)NIMG * SENS];
__device__ float  g_sn[(size_t)NIMG * UNITS];
__device__ float  g_sd[(size_t)NIMG * UNITS];
__device__ float4 g_sp[SENS * UNITS];
__device__ float4 g_rp[UNITS * UNITS];
__device__ float  g_skn[UNITS], g_skd[UNITS];
__device__ float  g_nc[UNITS], g_dc[UNITS], g_cmt[UNITS];
__device__ float  g_w1p[W1PSZ];
__device__ float  g_w2p[W2PSZ];

// ---------------- fast math helpers ----------------
__device__ __forceinline__ float rcpf(float x) {
    float y; asm("rcp.approx.f32 %0, %1;" : "=f"(y) : "f"(x)); return y;
}
__device__ __forceinline__ float tanhf_a(float x) {
    float y; asm("tanh.approx.f32 %0, %1;" : "=f"(y) : "f"(x)); return y;
}
__device__ __forceinline__ ull ffma2(ull a, ull b, ull c) {
    ull d; asm("fma.rn.f32x2 %0, %1, %2, %3;" : "=l"(d) : "l"(a), "l"(b), "l"(c));
    return d;
}
__device__ __forceinline__ float2 unpack2(ull v) {
    float2 r; asm("mov.b64 {%0, %1}, %2;" : "=f"(r.x), "=f"(r.y) : "l"(v));
    return r;
}

// ---------------- prep kernels ----------------
__global__ void k_prep_sens(const float* __restrict__ iw, const float* __restrict__ ib,
                            const float* __restrict__ ssig, const float* __restrict__ smu,
                            const float* __restrict__ sw, const float* __restrict__ serev,
                            const int* __restrict__ smask) {
    int idx = blockIdx.x * blockDim.x + threadIdx.x;
    if (idx >= SENS * UNITS) return;
    int k = idx / UNITS;
    float sg = ssig[idx], m = smu[idx];
    float w  = sw[idx] * (float)smask[idx];
    float A = 0.5f * sg * iw[k];
    float C = 0.5f * sg * (ib[k] - m);
    g_sp[idx] = make_float4(A, C, 0.5f * w * serev[idx], 0.5f * w);
}

__global__ void k_prep_rec(const float* __restrict__ sigma, const float* __restrict__ mu,
                           const float* __restrict__ wsyn, const float* __restrict__ erev,
                           const int* __restrict__ mask) {
    int idx = blockIdx.x * blockDim.x + threadIdx.x;
    if (idx >= UNITS * UNITS) return;
    float sg = sigma[idx], m = mu[idx];
    float w  = wsyn[idx] * (float)mask[idx];
    g_rp[idx] = make_float4(0.5f * sg, -0.5f * sg * m, 0.5f * w * erev[idx], 0.5f * w);
}

__global__ void __launch_bounds__(256) k_prep_const(const float* __restrict__ gleak,
                                                    const float* __restrict__ vleak,
                                                    const float* __restrict__ cm) {
    int u = blockIdx.x, tid = threadIdx.x;
    float kn = 0.f, kd = 0.f;
    for (int k = tid; k < SENS; k += 256) {
        float4 p = g_sp[k * UNITS + u];
        kn += p.z; kd += p.w;
    }
    #pragma unroll
    for (int o = 16; o > 0; o >>= 1) {
        kn += __shfl_xor_sync(0xffffffff, kn, o);
        kd += __shfl_xor_sync(0xffffffff, kd, o);
    }
    __shared__ float swn[8], swd[8];
    if ((tid & 31) == 0) { swn[tid >> 5] = kn; swd[tid >> 5] = kd; }
    __syncthreads();
    if (tid == 0) {
        float tn = 0.f, td = 0.f;
        #pragma unroll
        for (int i = 0; i < 8; i++) { tn += swn[i]; td += swd[i]; }
        g_skn[u] = tn; g_skd[u] = td;
        float rn = 0.f, rd = 0.f;
        for (int p = 0; p < UNITS; p++) { float4 q = g_rp[p * UNITS + u]; rn += q.z; rd += q.w; }
        float cmt = cm[u] * 6.f;
        g_cmt[u] = cmt;
        g_nc[u] = gleak[u] * vleak[u] + rn;
        g_dc[u] = cmt + gleak[u] + rd + 1e-8f;
    }
}

// pack both conv weight tensors oc-major in one launch
__global__ void k_prep_w(const float* __restrict__ w1, const float* __restrict__ w2) {
    int idx = blockIdx.x * blockDim.x + threadIdx.x;
    if (idx < 16 * 9 * 64) {
        int icp = idx / 576, rem = idx % 576, j = rem / 64, oc = rem % 64;
        g_w1p[idx * 2 + 0] = w1[(oc * 32 + 2 * icp) * 9 + j];
        g_w1p[idx * 2 + 1] = w1[(oc * 32 + 2 * icp + 1) * 9 + j];
    } else if (idx < 16 * 9 * 64 + 32 * 9 * 32) {
        int k = idx - 16 * 9 * 64;
        int icp = k / 288, rem = k % 288, j = rem / 32, oc = rem % 32;
        g_w2p[k * 2 + 0] = w2[(oc * 64 + 2 * icp) * 9 + j];
        g_w2p[k * 2 + 1] = w2[(oc * 64 + 2 * icp + 1) * 9 + j];
    }
}

// ---------------- fused CNN: conv0 + conv1 + conv2, one CTA per image ----------------
// 352 threads. smem (floats): simg[0,3456) sw0[3456,3744) sw1p[3744,22176) sc0[22176,57504)
// After conv1: sc1 reuses [3744,16416) (w1p dead), w2p reuses [22176,40608) (sc0 dead).
__global__ void __launch_bounds__(352) k_cnn(const float* __restrict__ image,
                                             const float* __restrict__ w0,
                                             const float* __restrict__ b0,
                                             const float* __restrict__ b1,
                                             const float* __restrict__ b2,
                                             const float* __restrict__ relpos) {
    extern __shared__ float sm[];
    float* simg = sm;                        // 3456
    float* sw0  = sm + 3456;                 // 288
    float* sw1p = sm + 3744;                 // 18432
    float* sc0  = sm + 3744 + W1PSZ;         // 35328
    int img = blockIdx.x, tid = threadIdx.x;

    {   // stage image + weights
        const float4* src = (const float4*)(image + (size_t)img * (H0 * W0));
        float4* d = (float4*)simg;
        for (int i = tid; i < (H0 * W0) / 4; i += 352) d[i] = src[i];
        for (int i = tid; i < 288; i += 352) sw0[i] = w0[i];
        const float4* ws = (const float4*)g_w1p;
        float4* dw = (float4*)sw1p;
        for (int i = tid; i < W1PSZ / 4; i += 352) dw[i] = ws[i];
    }
    __syncthreads();

    // ---- conv0 phase: warp per (icp, oy); lane = ox ----
    {
        int wid = tid >> 5, lane = tid & 31;
        for (int task = wid; task < 368; task += 11) {
            int icp = task / 23, oy = task % 23;
            float we[9], wo[9];
            #pragma unroll
            for (int j = 0; j < 9; j++) {
                we[j] = sw0[(2 * icp) * 9 + j];
                wo[j] = sw0[(2 * icp + 1) * 9 + j];
            }
            float be = __ldg(&b0[2 * icp]), bo = __ldg(&b0[2 * icp + 1]);
            float2* dst = (float2*)&sc0[icp * PLN + oy * PSTR];
            {
                float ae = be, ao = bo;
                #pragma unroll
                for (int ky = 0; ky < 3; ky++) {
                    const float* row = &simg[(2 * oy + ky) * W0 + 2 * lane];
                    #pragma unroll
                    for (int kx = 0; kx < 3; kx++) {
                        float r = row[kx];
                        ae = fmaf(we[ky * 3 + kx], r, ae);
                        ao = fmaf(wo[ky * 3 + kx], r, ao);
                    }
                }
                dst[lane] = make_float2(fmaxf(ae, 0.f), fmaxf(ao, 0.f));
            }
            if (lane < 4) {
                int ox = 32 + lane;
                float ae = be, ao = bo;
                if (lane < 3) {
                    #pragma unroll
                    for (int ky = 0; ky < 3; ky++) {
                        const float* row = &simg[(2 * oy + ky) * W0 + 2 * ox];
                        #pragma unroll
                        for (int kx = 0; kx < 3; kx++) {
                            float r = row[kx];
                            ae = fmaf(we[ky * 3 + kx], r, ae);
                            ao = fmaf(wo[ky * 3 + kx], r, ao);
                        }
                    }
                    dst[ox] = make_float2(fmaxf(ae, 0.f), fmaxf(ao, 0.f));
                } else {
                    dst[35] = make_float2(0.f, 0.f);
                }
            }
        }
    }
    __syncthreads();

    // ---- conv1 phase: warp = oy, lane = ocq; broadcast rows, coalesced weights ----
    int oy  = tid >> 5;          // 0..10
    int ocq = tid & 31;          // 0..31
    int oc0 = 2 * ocq;
    const ull* swq = (const ull*)sw1p;
    ull acc0[17], acc1[17];
    #pragma unroll
    for (int o = 0; o < 17; o++) { acc0[o] = 0ull; acc1[o] = 0ull; }

    #pragma unroll 1
    for (int icp = 0; icp < 16; icp++) {
        #pragma unroll
        for (int ky = 0; ky < 3; ky++) {
            int r = 2 * oy + ky;
            const float* rb = &sc0[icp * PLN + r * PSTR];
            ulonglong2 wv[3];
            #pragma unroll
            for (int kx = 0; kx < 3; kx++)
                wv[kx] = *(const ulonglong2*)&swq[(icp * 9 + ky * 3 + kx) * 64 + oc0];
            {   // chunk A: positions 0..19 -> outputs 0..8
                ull tA[20];
                const ulonglong2* pa = (const ulonglong2*)rb;
                #pragma unroll
                for (int j = 0; j < 10; j++) { ulonglong2 v = pa[j]; tA[2 * j] = v.x; tA[2 * j + 1] = v.y; }
                #pragma unroll
                for (int kx = 0; kx < 3; kx++) {
                    #pragma unroll
                    for (int o = 0; o < 9; o++) {
                        acc0[o] = ffma2(wv[kx].x, tA[2 * o + kx], acc0[o]);
                        acc1[o] = ffma2(wv[kx].y, tA[2 * o + kx], acc1[o]);
                    }
                }
            }
            {   // chunk B: positions 18..35 -> outputs 9..16
                ull tB[18];
                const ulonglong2* pb = (const ulonglong2*)(rb + 36);
                #pragma unroll
                for (int j = 0; j < 9; j++) { ulonglong2 v = pb[j]; tB[2 * j] = v.x; tB[2 * j + 1] = v.y; }
                #pragma unroll
                for (int kx = 0; kx < 3; kx++) {
                    #pragma unroll
                    for (int o = 9; o < 17; o++) {
                        acc0[o] = ffma2(wv[kx].x, tB[2 * o + kx - 18], acc0[o]);
                        acc1[o] = ffma2(wv[kx].y, tB[2 * o + kx - 18], acc1[o]);
                    }
                }
            }
        }
    }
    __syncthreads();   // all reads of sw1p / sc0 complete

    // ---- phase 3: conv1 epilogue -> smem sc1; stream w2p into retired sc0 region ----
    float* sc1  = sm + 3744;            // 12672 floats (over dead w1p)
    float* sw2p = sm + 3744 + W1PSZ;    // 18432 floats (over dead sc0)
    {
        float bb0 = __ldg(&b1[oc0]), bb1 = __ldg(&b1[oc0 + 1]);
        float2* outp = (float2*)&sc1[(ocq * 11 + oy) * 36];
        #pragma unroll
        for (int o = 0; o < 17; o++) {
            float2 e = unpack2(acc0[o]);
            float2 f = unpack2(acc1[o]);
            outp[o] = make_float2(fmaxf(e.x + e.y + bb0, 0.f), fmaxf(f.x + f.y + bb1, 0.f));
        }
        outp[17] = make_float2(0.f, 0.f);
        const float4* ws = (const float4*)g_w2p;
        float4* dw = (float4*)sw2p;
        for (int i = tid; i < W2PSZ / 4; i += 352) dw[i] = ws[i];
    }
    __syncthreads();

    // ---- conv2 phase: 10 warps; warp = (oy2, p), lane = oc ----
    if (tid < 320) {
        int w2i = tid >> 5;         // 0..9
        int oy2 = w2i >> 1;         // 0..4
        int p   = w2i & 1;          // 0..1
        int oc  = tid & 31;         // 0..31
        const ull* swq2 = (const ull*)sw2p;
        ull acc[4];
        #pragma unroll
        for (int o = 0; o < 4; o++) acc[o] = 0ull;
        #pragma unroll 1
        for (int icp = 0; icp < 32; icp++) {
            #pragma unroll
            for (int ky = 0; ky < 3; ky++) {
                int r = 2 * oy2 + ky;
                const ulonglong2* q = (const ulonglong2*)&sc1[icp * 396 + r * 36 + 16 * p];
                ull t[10];
                #pragma unroll
                for (int j = 0; j < 5; j++) { ulonglong2 v = q[j]; t[2 * j] = v.x; t[2 * j + 1] = v.y; }
                #pragma unroll
                for (int kx = 0; kx < 3; kx++) {
                    ull wk = swq2[(icp * 9 + ky * 3 + kx) * 32 + oc];
                    #pragma unroll
                    for (int o = 0; o < 4; o++)
                        acc[o] = ffma2(wk, t[2 * o + kx], acc[o]);
                }
            }
        }
        float bb = __ldg(&b2[oc]);
        float* out = &g_x[(size_t)img * SENS + oc * 40 + oy2 * 8 + 4 * p];
        #pragma unroll
        for (int o = 0; o < 4; o++) {
            float2 e = unpack2(acc[o]);
            out[o] = fmaxf(e.x + e.y + bb, 0.f);
        }
    }
    if (tid < 3) g_x[(size_t)img * SENS + 1280 + tid] = relpos[(size_t)img * 3 + tid];
}

// ---------------- sensory synapse precompute: 12 images/block ----------------
#define SCHUNK 96
#define SIMG   12
__global__ void __launch_bounds__(SIMG * UNITS) k_sens() {
    extern __shared__ float sm3[];
    float4* sp = (float4*)sm3;
    float*  xs = sm3 + SCHUNK * UNITS * 4;
    int tid = threadIdx.x;
    int img0 = blockIdx.x * SIMG;
    for (int i = tid; i < SIMG * SENS; i += SIMG * UNITS)
        xs[i] = g_x[(size_t)img0 * SENS + i];
    int u = tid % UNITS, t = tid / UNITS;
    float accn = 0.f, accd = 0.f;
    const float* xrow = &xs[t * SENS];
    for (int k0 = 0; k0 < SENS; k0 += SCHUNK) {
        int C = min(SCHUNK, SENS - k0);
        __syncthreads();
        for (int i = tid; i < C * UNITS; i += SIMG * UNITS) sp[i] = g_sp[k0 * UNITS + i];
        __syncthreads();
        #pragma unroll 4
        for (int kk = 0; kk < C; kk++) {
            float4 p = sp[kk * UNITS + u];
            float xv = xrow[k0 + kk];
            float tt = tanhf_a(fmaf(xv, p.x, p.y));
            accn = fmaf(p.z, tt, accn);
            accd = fmaf(p.w, tt, accd);
        }
    }
    g_sn[(size_t)(img0 + t) * UNITS + u] = g_skn[u] + accn;
    g_sd[(size_t)(img0 + t) * UNITS + u] = g_skd[u] + accd;
}

// ---------------- LTC recurrence + pooling + head ----------------
__global__ void __launch_bounds__(288) k_ltc(const float* __restrict__ wout,
                                             const float* __restrict__ bout,
                                             const float* __restrict__ whead,
                                             const float* __restrict__ bhead,
                                             float* __restrict__ out) {
    extern __shared__ float sm4[];
    float4* rp   = (float4*)sm4;
    float*  sn   = sm4 + 9216;
    float*  sd   = sn + 2304;
    float*  v    = sd + 2304;
    float*  redn = v + 48;
    float*  redd = redn + 288;
    float*  cmt  = redd + 288;
    float*  nc   = cmt + 48;
    float*  dc   = nc + 48;
    float*  outsum = dc + 48;
    int b = blockIdx.x, tid = threadIdx.x;
    for (int i = tid; i < UNITS * UNITS; i += 288) rp[i] = g_rp[i];
    for (int i = tid; i < NS * UNITS; i += 288) {
        sn[i] = g_sn[(size_t)b * NS * UNITS + i];
        sd[i] = g_sd[(size_t)b * NS * UNITS + i];
    }
    if (tid < UNITS) {
        v[tid] = 0.f;
        cmt[tid] = g_cmt[tid];
        nc[tid]  = g_nc[tid];
        dc[tid]  = g_dc[tid];
    }
    if (tid < 4) outsum[tid] = 0.f;
    __syncthreads();
    int u = tid % UNITS, g = tid / UNITS;
    for (int s = 0; s < NS; s++) {
        for (int it = 0; it < 6; it++) {
            float accn = 0.f, accd = 0.f;
            #pragma unroll
            for (int j = 0; j < 8; j++) {
                int p = g * 8 + j;
                float4 q = rp[p * UNITS + u];
                float tt = tanhf_a(fmaf(v[p], q.x, q.y));
                accn = fmaf(q.z, tt, accn);
                accd = fmaf(q.w, tt, accd);
            }
            redn[g * UNITS + u] = accn;
            redd[g * UNITS + u] = accd;
            __syncthreads();
            if (tid < UNITS) {
                float a = 0.f, d = 0.f;
                #pragma unroll
                for (int gg = 0; gg < 6; gg++) { a += redn[gg * UNITS + tid]; d += redd[gg * UNITS + tid]; }
                float vv  = v[tid];
                float num = fmaf(cmt[tid], vv, nc[tid]) + a + sn[s * UNITS + tid];
                float den = dc[tid] + d + sd[s * UNITS + tid];
                v[tid] = num * rcpf(den);
            }
            __syncthreads();
        }
        if (tid < 4) outsum[tid] += v[tid];
    }
    __syncthreads();
    if (tid == 0) {
        float p[4];
        #pragma unroll
        for (int m = 0; m < 4; m++)
            p[m] = outsum[m] * (1.f / 48.f) * wout[m] + bout[m];
        #pragma unroll
        for (int j = 0; j < 2; j++) {
            float h = bhead[j];
            #pragma unroll
            for (int m = 0; m < 4; m++) h = fmaf(p[m], whead[m * 2 + j], h);
            out[b * 2 + j] = tanhf(h);
        }
    }
}

// ---------------- launch ----------------
extern "C" void kernel_launch(void* const* d_in, const int* in_sizes, int n_in,
                              void* d_out, int out_size) {
    const float* image   = (const float*)d_in[0];
    const float* rel_pos = (const float*)d_in[1];
    const float* w0 = (const float*)d_in[2];
    const float* b0 = (const float*)d_in[3];
    const float* w1 = (const float*)d_in[4];
    const float* b1 = (const float*)d_in[5];
    const float* w2 = (const float*)d_in[6];
    const float* b2 = (const float*)d_in[7];
    const float* input_w = (const float*)d_in[8];
    const float* input_b = (const float*)d_in[9];
    const float* gleak = (const float*)d_in[10];
    const float* vleak = (const float*)d_in[11];
    const float* cm    = (const float*)d_in[12];
    const float* sigma = (const float*)d_in[13];
    const float* mu    = (const float*)d_in[14];
    const float* w_syn = (const float*)d_in[15];
    const float* erev  = (const float*)d_in[16];
    const float* s_sigma = (const float*)d_in[17];
    const float* s_mu    = (const float*)d_in[18];
    const float* s_w     = (const float*)d_in[19];
    const float* s_erev  = (const float*)d_in[20];
    const float* w_out = (const float*)d_in[21];
    const float* b_out = (const float*)d_in[22];
    const float* w_head = (const float*)d_in[23];
    const float* b_head = (const float*)d_in[24];
    const int* syn_mask  = (const int*)d_in[25];
    const int* sens_mask = (const int*)d_in[26];
    float* out = (float*)d_out;

    const int SM_A     = (3456 + 288 + W1PSZ + SC0SZ) * 4;      // 230016
    const int SM_SENS  = SCHUNK * UNITS * 16 + SIMG * SENS * 4;
    const int SM_LTC   = (9216 + 2304 + 2304 + 48 + 288 + 288 + 48 + 48 + 48 + 4) * 4;
    cudaFuncSetAttribute(k_cnn,  cudaFuncAttributeMaxDynamicSharedMemorySize, SM_A);
    cudaFuncSetAttribute(k_sens, cudaFuncAttributeMaxDynamicSharedMemorySize, SM_SENS);
    cudaFuncSetAttribute(k_ltc,  cudaFuncAttributeMaxDynamicSharedMemorySize, SM_LTC);

    k_prep_sens<<<(SENS * UNITS + 255) / 256, 256>>>(input_w, input_b, s_sigma, s_mu,
                                                     s_w, s_erev, sens_mask);
    k_prep_rec<<<(UNITS * UNITS + 255) / 256, 256>>>(sigma, mu, w_syn, erev, syn_mask);
    k_prep_const<<<UNITS, 256>>>(gleak, vleak, cm);
    k_prep_w<<<(16 * 9 * 64 + 32 * 9 * 32 + 255) / 256, 256>>>(w1, w2);
    k_cnn<<<NIMG, 352, SM_A>>>(image, w0, b0, b1, b2, rel_pos);
    k_sens<<<NIMG / SIMG, SIMG * UNITS, SM_SENS>>>();
    k_ltc<<<NB, 288, SM_LTC>>>(w_out, b_out, w_head, b_head, out);
}

// round 9
// speedup vs baseline: 3.0186x; 1.0500x over previous
#include <cuda_runtime.h>
#include <math.h>

typedef unsigned long long ull;

// ---------------- problem constants ----------------
#define NIMG   1536            // B*S
#define UNITS  48
#define SENS   1283
#define NB     32
#define NS     48
#define H0 48
#define W0 72

// sc0 interleaved ic-pair layout: [icp=16][row<=23 (alloc 24)][pos 0..35][2]
#define PSTR 92
#define PLN  (24*PSTR)          // 2208 floats per plane
#define SC0SZ (16*PLN)          // 35328 floats
#define W1PSZ (16*9*64*2)       // 18432 floats: [icp][j][oc] ull pairs
#define W2PSZ (32*9*32*2)       // 18432 floats: [icp][j][oc] ull
#define C1PSZ (32*11*18*2)      // 12672 floats: [ocq][y][x(pad18)][2] (smem only)

// ---------------- device scratch ----------------
__device__ float  g_x [(size_t)NIMG * SENS];
__device__ float  g_sn[(size_t)NIMG * UNITS];
__device__ float  g_sd[(size_t)NIMG * UNITS];
__device__ float4 g_sp[SENS * UNITS];
__device__ float4 g_rp[UNITS * UNITS];
__device__ float  g_skn[UNITS], g_skd[UNITS];
__device__ float  g_nc[UNITS], g_dc[UNITS], g_cmt[UNITS];
__device__ float  g_w1p[W1PSZ];
__device__ float  g_w2p[W2PSZ];

// ---------------- fast math helpers ----------------
__device__ __forceinline__ float rcpf(float x) {
    float y; asm("rcp.approx.f32 %0, %1;" : "=f"(y) : "f"(x)); return y;
}
__device__ __forceinline__ float tanhf_a(float x) {
    float y; asm("tanh.approx.f32 %0, %1;" : "=f"(y) : "f"(x)); return y;
}
__device__ __forceinline__ ull ffma2(ull a, ull b, ull c) {
    ull d; asm("fma.rn.f32x2 %0, %1, %2, %3;" : "=l"(d) : "l"(a), "l"(b), "l"(c));
    return d;
}
__device__ __forceinline__ float2 unpack2(ull v) {
    float2 r; asm("mov.b64 {%0, %1}, %2;" : "=f"(r.x), "=f"(r.y) : "l"(v));
    return r;
}

// ---------------- prep kernels ----------------
__global__ void k_prep_sens(const float* __restrict__ iw, const float* __restrict__ ib,
                            const float* __restrict__ ssig, const float* __restrict__ smu,
                            const float* __restrict__ sw, const float* __restrict__ serev,
                            const int* __restrict__ smask) {
    int idx = blockIdx.x * blockDim.x + threadIdx.x;
    if (idx >= SENS * UNITS) return;
    int k = idx / UNITS;
    float sg = ssig[idx], m = smu[idx];
    float w  = sw[idx] * (float)smask[idx];
    float A = 0.5f * sg * iw[k];
    float C = 0.5f * sg * (ib[k] - m);
    g_sp[idx] = make_float4(A, C, 0.5f * w * serev[idx], 0.5f * w);
}

__global__ void k_prep_rec(const float* __restrict__ sigma, const float* __restrict__ mu,
                           const float* __restrict__ wsyn, const float* __restrict__ erev,
                           const int* __restrict__ mask) {
    int idx = blockIdx.x * blockDim.x + threadIdx.x;
    if (idx >= UNITS * UNITS) return;
    float sg = sigma[idx], m = mu[idx];
    float w  = wsyn[idx] * (float)mask[idx];
    g_rp[idx] = make_float4(0.5f * sg, -0.5f * sg * m, 0.5f * w * erev[idx], 0.5f * w);
}

__global__ void __launch_bounds__(256) k_prep_const(const float* __restrict__ gleak,
                                                    const float* __restrict__ vleak,
                                                    const float* __restrict__ cm) {
    int u = blockIdx.x, tid = threadIdx.x;
    float kn = 0.f, kd = 0.f;
    for (int k = tid; k < SENS; k += 256) {
        float4 p = g_sp[k * UNITS + u];
        kn += p.z; kd += p.w;
    }
    #pragma unroll
    for (int o = 16; o > 0; o >>= 1) {
        kn += __shfl_xor_sync(0xffffffff, kn, o);
        kd += __shfl_xor_sync(0xffffffff, kd, o);
    }
    __shared__ float swn[8], swd[8];
    if ((tid & 31) == 0) { swn[tid >> 5] = kn; swd[tid >> 5] = kd; }
    __syncthreads();
    if (tid == 0) {
        float tn = 0.f, td = 0.f;
        #pragma unroll
        for (int i = 0; i < 8; i++) { tn += swn[i]; td += swd[i]; }
        g_skn[u] = tn; g_skd[u] = td;
        float rn = 0.f, rd = 0.f;
        for (int p = 0; p < UNITS; p++) { float4 q = g_rp[p * UNITS + u]; rn += q.z; rd += q.w; }
        float cmt = cm[u] * 6.f;
        g_cmt[u] = cmt;
        g_nc[u] = gleak[u] * vleak[u] + rn;
        g_dc[u] = cmt + gleak[u] + rd + 1e-8f;
    }
}

// pack both conv weight tensors oc-major in one launch
__global__ void k_prep_w(const float* __restrict__ w1, const float* __restrict__ w2) {
    int idx = blockIdx.x * blockDim.x + threadIdx.x;
    if (idx < 16 * 9 * 64) {
        int icp = idx / 576, rem = idx % 576, j = rem / 64, oc = rem % 64;
        g_w1p[idx * 2 + 0] = w1[(oc * 32 + 2 * icp) * 9 + j];
        g_w1p[idx * 2 + 1] = w1[(oc * 32 + 2 * icp + 1) * 9 + j];
    } else if (idx < 16 * 9 * 64 + 32 * 9 * 32) {
        int k = idx - 16 * 9 * 64;
        int icp = k / 288, rem = k % 288, j = rem / 32, oc = rem % 32;
        g_w2p[k * 2 + 0] = w2[(oc * 64 + 2 * icp) * 9 + j];
        g_w2p[k * 2 + 1] = w2[(oc * 64 + 2 * icp + 1) * 9 + j];
    }
}

// ---------------- fused CNN: conv0 + conv1 + conv2, one CTA per image ----------------
// 704 threads (22 warps). conv1: warp = (oy, ocHalf), lane = oc; 1 oc per lane.
__global__ void __launch_bounds__(704) k_cnn(const float* __restrict__ image,
                                             const float* __restrict__ w0,
                                             const float* __restrict__ b0,
                                             const float* __restrict__ b1,
                                             const float* __restrict__ b2,
                                             const float* __restrict__ relpos) {
    extern __shared__ float sm[];
    float* simg = sm;                        // 3456
    float* sw0  = sm + 3456;                 // 288
    float* sw1p = sm + 3744;                 // 18432
    float* sc0  = sm + 3744 + W1PSZ;         // 35328
    int img = blockIdx.x, tid = threadIdx.x;

    {   // stage image + weights
        const float4* src = (const float4*)(image + (size_t)img * (H0 * W0));
        float4* d = (float4*)simg;
        for (int i = tid; i < (H0 * W0) / 4; i += 704) d[i] = src[i];
        for (int i = tid; i < 288; i += 704) sw0[i] = w0[i];
        const float4* ws = (const float4*)g_w1p;
        float4* dw = (float4*)sw1p;
        for (int i = tid; i < W1PSZ / 4; i += 704) dw[i] = ws[i];
    }
    __syncthreads();

    // ---- conv0 phase: warp per (icp, oy); lane = ox ----
    {
        int wid = tid >> 5, lane = tid & 31;
        for (int task = wid; task < 368; task += 22) {
            int icp = task / 23, oyc = task % 23;
            float we[9], wo[9];
            #pragma unroll
            for (int j = 0; j < 9; j++) {
                we[j] = sw0[(2 * icp) * 9 + j];
                wo[j] = sw0[(2 * icp + 1) * 9 + j];
            }
            float be = __ldg(&b0[2 * icp]), bo = __ldg(&b0[2 * icp + 1]);
            float2* dst = (float2*)&sc0[icp * PLN + oyc * PSTR];
            {
                float ae = be, ao = bo;
                #pragma unroll
                for (int ky = 0; ky < 3; ky++) {
                    const float* row = &simg[(2 * oyc + ky) * W0 + 2 * lane];
                    #pragma unroll
                    for (int kx = 0; kx < 3; kx++) {
                        float r = row[kx];
                        ae = fmaf(we[ky * 3 + kx], r, ae);
                        ao = fmaf(wo[ky * 3 + kx], r, ao);
                    }
                }
                dst[lane] = make_float2(fmaxf(ae, 0.f), fmaxf(ao, 0.f));
            }
            if (lane < 4) {
                int ox = 32 + lane;
                float ae = be, ao = bo;
                if (lane < 3) {
                    #pragma unroll
                    for (int ky = 0; ky < 3; ky++) {
                        const float* row = &simg[(2 * oyc + ky) * W0 + 2 * ox];
                        #pragma unroll
                        for (int kx = 0; kx < 3; kx++) {
                            float r = row[kx];
                            ae = fmaf(we[ky * 3 + kx], r, ae);
                            ao = fmaf(wo[ky * 3 + kx], r, ao);
                        }
                    }
                    dst[ox] = make_float2(fmaxf(ae, 0.f), fmaxf(ao, 0.f));
                } else {
                    dst[35] = make_float2(0.f, 0.f);
                }
            }
        }
    }
    __syncthreads();

    // ---- conv1 phase: 22 warps; warp = (oy, ocHalf), lane -> oc; 1 oc per lane ----
    int w1i  = tid >> 5;                 // 0..21
    int lane = tid & 31;
    int oy   = w1i % 11;                 // 0..10
    int och  = w1i / 11;                 // 0..1
    int oc   = och * 32 + lane;          // 0..63
    const ull* swq = (const ull*)sw1p;
    ull acc[17];
    #pragma unroll
    for (int o = 0; o < 17; o++) acc[o] = 0ull;

    #pragma unroll 1
    for (int icp = 0; icp < 16; icp++) {
        #pragma unroll
        for (int ky = 0; ky < 3; ky++) {
            int r = 2 * oy + ky;
            const ull* rb = (const ull*)&sc0[icp * PLN + r * PSTR];
            ull wv[3];
            #pragma unroll
            for (int kx = 0; kx < 3; kx++)
                wv[kx] = swq[(icp * 9 + ky * 3 + kx) * 64 + oc];
            {   // chunk 1: positions 0..12 -> outputs 0..5
                ull t[13];
                const ulonglong2* p2 = (const ulonglong2*)rb;
                #pragma unroll
                for (int j = 0; j < 6; j++) { ulonglong2 v = p2[j]; t[2 * j] = v.x; t[2 * j + 1] = v.y; }
                t[12] = rb[12];
                #pragma unroll
                for (int kx = 0; kx < 3; kx++)
                    #pragma unroll
                    for (int o = 0; o < 6; o++)
                        acc[o] = ffma2(wv[kx], t[2 * o + kx], acc[o]);
            }
            {   // chunk 2: positions 12..24 -> outputs 6..11
                ull t[13];
                const ulonglong2* p2 = (const ulonglong2*)(rb + 12);
                #pragma unroll
                for (int j = 0; j < 6; j++) { ulonglong2 v = p2[j]; t[2 * j] = v.x; t[2 * j + 1] = v.y; }
                t[12] = rb[24];
                #pragma unroll
                for (int kx = 0; kx < 3; kx++)
                    #pragma unroll
                    for (int o = 6; o < 12; o++)
                        acc[o] = ffma2(wv[kx], t[2 * (o - 6) + kx], acc[o]);
            }
            {   // chunk 3: positions 24..34 -> outputs 12..16
                ull t[11];
                const ulonglong2* p2 = (const ulonglong2*)(rb + 24);
                #pragma unroll
                for (int j = 0; j < 5; j++) { ulonglong2 v = p2[j]; t[2 * j] = v.x; t[2 * j + 1] = v.y; }
                t[10] = rb[34];
                #pragma unroll
                for (int kx = 0; kx < 3; kx++)
                    #pragma unroll
                    for (int o = 12; o < 17; o++)
                        acc[o] = ffma2(wv[kx], t[2 * (o - 12) + kx], acc[o]);
            }
        }
    }
    __syncthreads();   // all reads of sw1p / sc0 complete

    // ---- phase 3: conv1 epilogue -> smem sc1; stream w2p into retired sc0 region ----
    float* sc1  = sm + 3744;            // 12672 floats (over dead w1p)
    float* sw2p = sm + 3744 + W1PSZ;    // 18432 floats (over dead sc0)
    {
        float bb = __ldg(&b1[oc]);
        float* outp = &sc1[((oc >> 1) * 11 + oy) * 36 + (oc & 1)];
        #pragma unroll
        for (int o = 0; o < 17; o++) {
            float2 e = unpack2(acc[o]);
            outp[2 * o] = fmaxf(e.x + e.y + bb, 0.f);
        }
        outp[34] = 0.f;   // pad position 17 (both parities covered)
        const float4* ws = (const float4*)g_w2p;
        float4* dw = (float4*)sw2p;
        for (int i = tid; i < W2PSZ / 4; i += 704) dw[i] = ws[i];
    }
    __syncthreads();

    // ---- conv2 phase: 10 warps; warp = (oy2, p), lane = oc ----
    if (tid < 320) {
        int w2i = tid >> 5;         // 0..9
        int oy2 = w2i >> 1;         // 0..4
        int p   = w2i & 1;          // 0..1
        int oc2 = tid & 31;         // 0..31
        const ull* swq2 = (const ull*)sw2p;
        ull acc2[4];
        #pragma unroll
        for (int o = 0; o < 4; o++) acc2[o] = 0ull;
        #pragma unroll 1
        for (int icp = 0; icp < 32; icp++) {
            #pragma unroll
            for (int ky = 0; ky < 3; ky++) {
                int r = 2 * oy2 + ky;
                const ulonglong2* q = (const ulonglong2*)&sc1[icp * 396 + r * 36 + 16 * p];
                ull t[10];
                #pragma unroll
                for (int j = 0; j < 5; j++) { ulonglong2 v = q[j]; t[2 * j] = v.x; t[2 * j + 1] = v.y; }
                #pragma unroll
                for (int kx = 0; kx < 3; kx++) {
                    ull wk = swq2[(icp * 9 + ky * 3 + kx) * 32 + oc2];
                    #pragma unroll
                    for (int o = 0; o < 4; o++)
                        acc2[o] = ffma2(wk, t[2 * o + kx], acc2[o]);
                }
            }
        }
        float bb = __ldg(&b2[oc2]);
        float* out = &g_x[(size_t)img * SENS + oc2 * 40 + oy2 * 8 + 4 * p];
        #pragma unroll
        for (int o = 0; o < 4; o++) {
            float2 e = unpack2(acc2[o]);
            out[o] = fmaxf(e.x + e.y + bb, 0.f);
        }
    }
    if (tid < 3) g_x[(size_t)img * SENS + 1280 + tid] = relpos[(size_t)img * 3 + tid];
}

// ---------------- sensory synapse precompute: 12 images/block ----------------
#define SCHUNK 96
#define SIMG   12
__global__ void __launch_bounds__(SIMG * UNITS) k_sens() {
    extern __shared__ float sm3[];
    float4* sp = (float4*)sm3;
    float*  xs = sm3 + SCHUNK * UNITS * 4;
    int tid = threadIdx.x;
    int img0 = blockIdx.x * SIMG;
    for (int i = tid; i < SIMG * SENS; i += SIMG * UNITS)
        xs[i] = g_x[(size_t)img0 * SENS + i];
    int u = tid % UNITS, t = tid / UNITS;
    float accn = 0.f, accd = 0.f;
    const float* xrow = &xs[t * SENS];
    for (int k0 = 0; k0 < SENS; k0 += SCHUNK) {
        int C = min(SCHUNK, SENS - k0);
        __syncthreads();
        for (int i = tid; i < C * UNITS; i += SIMG * UNITS) sp[i] = g_sp[k0 * UNITS + i];
        __syncthreads();
        #pragma unroll 4
        for (int kk = 0; kk < C; kk++) {
            float4 p = sp[kk * UNITS + u];
            float xv = xrow[k0 + kk];
            float tt = tanhf_a(fmaf(xv, p.x, p.y));
            accn = fmaf(p.z, tt, accn);
            accd = fmaf(p.w, tt, accd);
        }
    }
    g_sn[(size_t)(img0 + t) * UNITS + u] = g_skn[u] + accn;
    g_sd[(size_t)(img0 + t) * UNITS + u] = g_skd[u] + accd;
}

// ---------------- LTC recurrence + pooling + head ----------------
__global__ void __launch_bounds__(288) k_ltc(const float* __restrict__ wout,
                                             const float* __restrict__ bout,
                                             const float* __restrict__ whead,
                                             const float* __restrict__ bhead,
                                             float* __restrict__ out) {
    extern __shared__ float sm4[];
    float4* rp   = (float4*)sm4;
    float*  sn   = sm4 + 9216;
    float*  sd   = sn + 2304;
    float*  v    = sd + 2304;
    float*  redn = v + 48;
    float*  redd = redn + 288;
    float*  cmt  = redd + 288;
    float*  nc   = cmt + 48;
    float*  dc   = nc + 48;
    float*  outsum = dc + 48;
    int b = blockIdx.x, tid = threadIdx.x;
    for (int i = tid; i < UNITS * UNITS; i += 288) rp[i] = g_rp[i];
    for (int i = tid; i < NS * UNITS; i += 288) {
        sn[i] = g_sn[(size_t)b * NS * UNITS + i];
        sd[i] = g_sd[(size_t)b * NS * UNITS + i];
    }
    if (tid < UNITS) {
        v[tid] = 0.f;
        cmt[tid] = g_cmt[tid];
        nc[tid]  = g_nc[tid];
        dc[tid]  = g_dc[tid];
    }
    if (tid < 4) outsum[tid] = 0.f;
    __syncthreads();
    int u = tid % UNITS, g = tid / UNITS;
    for (int s = 0; s < NS; s++) {
        for (int it = 0; it < 6; it++) {
            float accn = 0.f, accd = 0.f;
            #pragma unroll
            for (int j = 0; j < 8; j++) {
                int p = g * 8 + j;
                float4 q = rp[p * UNITS + u];
                float tt = tanhf_a(fmaf(v[p], q.x, q.y));
                accn = fmaf(q.z, tt, accn);
                accd = fmaf(q.w, tt, accd);
            }
            redn[g * UNITS + u] = accn;
            redd[g * UNITS + u] = accd;
            __syncthreads();
            if (tid < UNITS) {
                float a = 0.f, d = 0.f;
                #pragma unroll
                for (int gg = 0; gg < 6; gg++) { a += redn[gg * UNITS + tid]; d += redd[gg * UNITS + tid]; }
                float vv  = v[tid];
                float num = fmaf(cmt[tid], vv, nc[tid]) + a + sn[s * UNITS + tid];
                float den = dc[tid] + d + sd[s * UNITS + tid];
                v[tid] = num * rcpf(den);
            }
            __syncthreads();
        }
        if (tid < 4) outsum[tid] += v[tid];
    }
    __syncthreads();
    if (tid == 0) {
        float p[4];
        #pragma unroll
        for (int m = 0; m < 4; m++)
            p[m] = outsum[m] * (1.f / 48.f) * wout[m] + bout[m];
        #pragma unroll
        for (int j = 0; j < 2; j++) {
            float h = bhead[j];
            #pragma unroll
            for (int m = 0; m < 4; m++) h = fmaf(p[m], whead[m * 2 + j], h);
            out[b * 2 + j] = tanhf(h);
        }
    }
}

// ---------------- launch ----------------
extern "C" void kernel_launch(void* const* d_in, const int* in_sizes, int n_in,
                              void* d_out, int out_size) {
    const float* image   = (const float*)d_in[0];
    const float* rel_pos = (const float*)d_in[1];
    const float* w0 = (const float*)d_in[2];
    const float* b0 = (const float*)d_in[3];
    const float* w1 = (const float*)d_in[4];
    const float* b1 = (const float*)d_in[5];
    const float* w2 = (const float*)d_in[6];
    const float* b2 = (const float*)d_in[7];
    const float* input_w = (const float*)d_in[8];
    const float* input_b = (const float*)d_in[9];
    const float* gleak = (const float*)d_in[10];
    const float* vleak = (const float*)d_in[11];
    const float* cm    = (const float*)d_in[12];
    const float* sigma = (const float*)d_in[13];
    const float* mu    = (const float*)d_in[14];
    const float* w_syn = (const float*)d_in[15];
    const float* erev  = (const float*)d_in[16];
    const float* s_sigma = (const float*)d_in[17];
    const float* s_mu    = (const float*)d_in[18];
    const float* s_w     = (const float*)d_in[19];
    const float* s_erev  = (const float*)d_in[20];
    const float* w_out = (const float*)d_in[21];
    const float* b_out = (const float*)d_in[22];
    const float* w_head = (const float*)d_in[23];
    const float* b_head = (const float*)d_in[24];
    const int* syn_mask  = (const int*)d_in[25];
    const int* sens_mask = (const int*)d_in[26];
    float* out = (float*)d_out;

    const int SM_A     = (3456 + 288 + W1PSZ + SC0SZ) * 4;      // 230016
    const int SM_SENS  = SCHUNK * UNITS * 16 + SIMG * SENS * 4;
    const int SM_LTC   = (9216 + 2304 + 2304 + 48 + 288 + 288 + 48 + 48 + 48 + 4) * 4;
    cudaFuncSetAttribute(k_cnn,  cudaFuncAttributeMaxDynamicSharedMemorySize, SM_A);
    cudaFuncSetAttribute(k_sens, cudaFuncAttributeMaxDynamicSharedMemorySize, SM_SENS);
    cudaFuncSetAttribute(k_ltc,  cudaFuncAttributeMaxDynamicSharedMemorySize, SM_LTC);

    // order chosen so k_cnn is the 4th launch (the one ncu captures)
    k_prep_w<<<(16 * 9 * 64 + 32 * 9 * 32 + 255) / 256, 256>>>(w1, w2);
    k_prep_sens<<<(SENS * UNITS + 255) / 256, 256>>>(input_w, input_b, s_sigma, s_mu,
                                                     s_w, s_erev, sens_mask);
    k_prep_rec<<<(UNITS * UNITS + 255) / 256, 256>>>(sigma, mu, w_syn, erev, syn_mask);
    k_cnn<<<NIMG, 704, SM_A>>>(image, w0, b0, b1, b2, rel_pos);
    k_prep_const<<<UNITS, 256>>>(gleak, vleak, cm);
    k_sens<<<NIMG / SIMG, SIMG * UNITS, SM_SENS>>>();
    k_ltc<<<NB, 288, SM_LTC>>>(w_out, b_out, w_head, b_head, out);
}